// round 3
// baseline (speedup 1.0000x reference)
#include <cuda_runtime.h>

#define NN 50000
#define EE 800000
#define DD 128
#define GB ((NN + 63) / 64)       // 782 gemm blocks
#define NB_SCAN ((NN + 511) / 512) // 98 scan blocks

// ---------------- scratch (device globals: allocation-free) ----------------
__device__ float g_xh[NN * DD];
__device__ float g_Tx1[NN * DD];
__device__ float g_mean[NN * DD];
__device__ float g_o1[NN * DD];
__device__ float g_s[NN * DD];
__device__ float g_deg[NN];
__device__ float g_dis[NN];
__device__ int   g_cnt[NN];
__device__ int   g_fill[NN];
__device__ int   g_rowptr[NN + 1];
__device__ int   g_bsum[128];
__device__ int   g_csrc[EE];
__device__ float g_cw[EE];

// ---------------- small kernels ----------------
__global__ void zero_kernel() {
    int i = blockIdx.x * blockDim.x + threadIdx.x;
    if (i < NN) { g_deg[i] = 0.f; g_cnt[i] = 0; g_fill[i] = 0; }
}

__global__ void hist_kernel(const int* __restrict__ ei, const float* __restrict__ ew) {
    int e = blockIdx.x * blockDim.x + threadIdx.x;
    if (e < EE) {
        atomicAdd(&g_deg[ei[e]], ew[e]);        // weighted out-degree at src
        atomicAdd(&g_cnt[ei[EE + e]], 1);       // in-degree count at dst
    }
}

__global__ void dis_kernel() {
    int i = blockIdx.x * blockDim.x + threadIdx.x;
    if (i < NN) {
        float d = g_deg[i];
        g_dis[i] = (d > 0.f) ? rsqrtf(d) : 0.f;
    }
}

__global__ void scan1_kernel() {
    __shared__ int sm[512];
    int t = threadIdx.x, b = blockIdx.x;
    int i = b * 512 + t;
    int v = (i < NN) ? g_cnt[i] : 0;
    sm[t] = v;
    __syncthreads();
    #pragma unroll
    for (int off = 1; off < 512; off <<= 1) {
        int x = (t >= off) ? sm[t - off] : 0;
        __syncthreads();
        if (t >= off) sm[t] += x;
        __syncthreads();
    }
    if (i < NN) g_rowptr[i + 1] = sm[t];
    if (t == 511) g_bsum[b] = sm[511];
}

__global__ void scan2_kernel() {   // single block, exclusive scan of block sums
    __shared__ int sm[128];
    int t = threadIdx.x;
    int v = (t < NB_SCAN) ? g_bsum[t] : 0;
    sm[t] = v;
    __syncthreads();
    #pragma unroll
    for (int off = 1; off < 128; off <<= 1) {
        int x = (t >= off) ? sm[t - off] : 0;
        __syncthreads();
        sm[t] += x;
        __syncthreads();
    }
    if (t < NB_SCAN) g_bsum[t] = sm[t] - v;   // exclusive
}

__global__ void scan3_kernel() {
    int i = blockIdx.x * blockDim.x + threadIdx.x;
    if (i < NN) {
        if (i == 0) g_rowptr[0] = 0;
        g_rowptr[i + 1] += g_bsum[i >> 9];
    }
}

__global__ void fill_kernel(const int* __restrict__ ei, const float* __restrict__ ew) {
    int e = blockIdx.x * blockDim.x + threadIdx.x;
    if (e < EE) {
        int d = ei[EE + e];
        int pos = g_rowptr[d] + atomicAdd(&g_fill[d], 1);
        g_csrc[pos] = ei[e];
        g_cw[pos]   = ew[e];
    }
}

// warp-per-dst gather/accumulate: Tx1 (Cheb) and mean (SAGE) in one pass.
__global__ void aggregate_kernel() {
    int warp = (blockIdx.x * blockDim.x + threadIdx.x) >> 5;
    int lane = threadIdx.x & 31;
    if (warp >= NN) return;
    int beg = g_rowptr[warp], end = g_rowptr[warp + 1];
    float dd = g_dis[warp];
    float4 aT = make_float4(0.f, 0.f, 0.f, 0.f);
    float4 aM = make_float4(0.f, 0.f, 0.f, 0.f);
    const float4* xh4 = (const float4*)g_xh;
    #pragma unroll 4
    for (int e = beg; e < end; ++e) {
        int s = g_csrc[e];
        float w = g_cw[e];
        float nrm = -g_dis[s] * w * dd;
        float4 v = xh4[s * 32 + lane];
        aT.x += nrm * v.x; aT.y += nrm * v.y; aT.z += nrm * v.z; aT.w += nrm * v.w;
        aM.x += w   * v.x; aM.y += w   * v.y; aM.z += w   * v.z; aM.w += w   * v.w;
    }
    ((float4*)g_Tx1)[warp * 32 + lane] = aT;
    float inv = 1.0f / fmaxf((float)g_cnt[warp], 1.0f);
    aM.x *= inv; aM.y *= inv; aM.z *= inv; aM.w *= inv;
    ((float4*)g_mean)[warp * 32 + lane] = aM;
}

// ---------------- GEMM: out = [ADDC? C +] [LEAKY? lrelu](A@W1^T [+ B@W2^T] + bias)
// Block: 64 rows x 128 cols, 256 threads; thread = 8 rows x 4 cols (cols tx+32j).
template <bool DUAL, bool LEAKY, bool ADDC>
__global__ void __launch_bounds__(256) gemm_kernel(
    const float* __restrict__ A, const float* __restrict__ B,
    const float* __restrict__ C,
    const float* __restrict__ W1, const float* __restrict__ W2,
    const float* __restrict__ bias, float* __restrict__ out)
{
    extern __shared__ float smem[];
    float* As  = smem;
    float* Bs  = As + 64 * DD;                          // used iff DUAL
    float* W1s = DUAL ? (Bs + 64 * DD) : (As + 64 * DD);
    float* W2s = W1s + DD * 129;

    const int tid = threadIdx.x;
    const int tx = tid & 31, ty = tid >> 5;
    const int rowBase = blockIdx.x * 64;

    {
        const float4* Ag = (const float4*)A;
        for (int idx = tid; idx < 64 * 32; idx += 256) {
            int r = idx >> 5, gr = rowBase + r;
            float4 v = (gr < NN) ? Ag[gr * 32 + (idx & 31)] : make_float4(0.f, 0.f, 0.f, 0.f);
            ((float4*)As)[idx] = v;
        }
    }
    if (DUAL) {
        const float4* Bg = (const float4*)B;
        for (int idx = tid; idx < 64 * 32; idx += 256) {
            int r = idx >> 5, gr = rowBase + r;
            float4 v = (gr < NN) ? Bg[gr * 32 + (idx & 31)] : make_float4(0.f, 0.f, 0.f, 0.f);
            ((float4*)Bs)[idx] = v;
        }
    }
    {
        const float4* Wg = (const float4*)W1;
        for (int idx = tid; idx < 128 * 32; idx += 256) {
            int o = idx >> 5, c4 = idx & 31;
            float4 v = Wg[idx];
            float* p = &W1s[o * 129 + c4 * 4];
            p[0] = v.x; p[1] = v.y; p[2] = v.z; p[3] = v.w;
        }
    }
    if (DUAL) {
        const float4* Wg = (const float4*)W2;
        for (int idx = tid; idx < 128 * 32; idx += 256) {
            int o = idx >> 5, c4 = idx & 31;
            float4 v = Wg[idx];
            float* p = &W2s[o * 129 + c4 * 4];
            p[0] = v.x; p[1] = v.y; p[2] = v.z; p[3] = v.w;
        }
    }
    __syncthreads();

    float acc[8][4];
    #pragma unroll
    for (int r = 0; r < 8; ++r)
        #pragma unroll
        for (int j = 0; j < 4; ++j) acc[r][j] = 0.f;

    #pragma unroll 8
    for (int k = 0; k < DD; ++k) {
        float w0 = W1s[(tx      ) * 129 + k];
        float w1 = W1s[(tx + 32 ) * 129 + k];
        float w2 = W1s[(tx + 64 ) * 129 + k];
        float w3 = W1s[(tx + 96 ) * 129 + k];
        #pragma unroll
        for (int r = 0; r < 8; ++r) {
            float a = As[(ty + r * 8) * DD + k];
            acc[r][0] += a * w0; acc[r][1] += a * w1;
            acc[r][2] += a * w2; acc[r][3] += a * w3;
        }
    }
    if (DUAL) {
        #pragma unroll 8
        for (int k = 0; k < DD; ++k) {
            float w0 = W2s[(tx      ) * 129 + k];
            float w1 = W2s[(tx + 32 ) * 129 + k];
            float w2 = W2s[(tx + 64 ) * 129 + k];
            float w3 = W2s[(tx + 96 ) * 129 + k];
            #pragma unroll
            for (int r = 0; r < 8; ++r) {
                float a = Bs[(ty + r * 8) * DD + k];
                acc[r][0] += a * w0; acc[r][1] += a * w1;
                acc[r][2] += a * w2; acc[r][3] += a * w3;
            }
        }
    }

    float b0 = bias[tx], b1 = bias[tx + 32], b2 = bias[tx + 64], b3 = bias[tx + 96];
    #pragma unroll
    for (int r = 0; r < 8; ++r) {
        int gr = rowBase + ty + r * 8;
        if (gr < NN) {
            float v0 = acc[r][0] + b0, v1 = acc[r][1] + b1;
            float v2 = acc[r][2] + b2, v3 = acc[r][3] + b3;
            if (LEAKY) {
                v0 = (v0 > 0.f) ? v0 : 0.01f * v0;
                v1 = (v1 > 0.f) ? v1 : 0.01f * v1;
                v2 = (v2 > 0.f) ? v2 : 0.01f * v2;
                v3 = (v3 > 0.f) ? v3 : 0.01f * v3;
            }
            if (ADDC) {
                v0 += C[gr * DD + tx];
                v1 += C[gr * DD + tx + 32];
                v2 += C[gr * DD + tx + 64];
                v3 += C[gr * DD + tx + 96];
            }
            out[gr * DD + tx      ] = v0;
            out[gr * DD + tx + 32 ] = v1;
            out[gr * DD + tx + 64 ] = v2;
            out[gr * DD + tx + 96 ] = v3;
        }
    }
}

// ---------------- launch ----------------
extern "C" void kernel_launch(void* const* d_in, const int* in_sizes, int n_in,
                              void* d_out, int out_size)
{
    (void)in_sizes; (void)n_in;
    // inputs: h, x, edge_index, edge_weight, Wp, bp, Wc0, Wc1, bc, Wrel, brel, Wroot, Wl, bl
    const float* x    = (const float*)d_in[1];
    const int*   ei   = (const int*)  d_in[2];
    const float* ew   = (const float*)d_in[3];
    const float* Wp   = (const float*)d_in[4];
    const float* bp   = (const float*)d_in[5];
    const float* Wc0  = (const float*)d_in[6];
    const float* Wc1  = (const float*)d_in[7];
    const float* bc   = (const float*)d_in[8];
    const float* Wrel = (const float*)d_in[9];
    const float* brel = (const float*)d_in[10];
    const float* Wroot= (const float*)d_in[11];
    const float* Wl   = (const float*)d_in[12];
    const float* bl   = (const float*)d_in[13];
    float* out = (float*)d_out;

    void *p_xh, *p_Tx1, *p_mean, *p_o1, *p_s;
    cudaGetSymbolAddress(&p_xh,   g_xh);
    cudaGetSymbolAddress(&p_Tx1,  g_Tx1);
    cudaGetSymbolAddress(&p_mean, g_mean);
    cudaGetSymbolAddress(&p_o1,   g_o1);
    cudaGetSymbolAddress(&p_s,    g_s);

    const size_t smem1 = (size_t)(64 * DD + DD * 129) * sizeof(float);       // ~98.8 KB
    const size_t smem2 = (size_t)(2 * 64 * DD + 2 * DD * 129) * sizeof(float); // ~197.6 KB
    cudaFuncSetAttribute(gemm_kernel<false, false, false>,
                         cudaFuncAttributeMaxDynamicSharedMemorySize, (int)smem1);
    cudaFuncSetAttribute(gemm_kernel<true, true, false>,
                         cudaFuncAttributeMaxDynamicSharedMemorySize, (int)smem2);
    cudaFuncSetAttribute(gemm_kernel<true, true, true>,
                         cudaFuncAttributeMaxDynamicSharedMemorySize, (int)smem2);

    const int TB = 256;
    // graph structure / degrees
    zero_kernel<<<(NN + TB - 1) / TB, TB>>>();
    hist_kernel<<<(EE + TB - 1) / TB, TB>>>(ei, ew);
    dis_kernel<<<(NN + TB - 1) / TB, TB>>>();
    scan1_kernel<<<NB_SCAN, 512>>>();
    scan2_kernel<<<1, 128>>>();
    scan3_kernel<<<(NN + TB - 1) / TB, TB>>>();
    fill_kernel<<<(EE + TB - 1) / TB, TB>>>(ei, ew);

    // xh = x @ Wp^T + bp
    gemm_kernel<false, false, false><<<GB, TB, smem1>>>(
        x, nullptr, nullptr, Wp, nullptr, bp, (float*)p_xh);

    // Tx1 + mean in one CSR gather pass
    aggregate_kernel<<<(NN * 32 + TB - 1) / TB, TB>>>();

    // o1 = lrelu(xh@Wc0^T + Tx1@Wc1^T + bc)
    gemm_kernel<true, true, false><<<GB, TB, smem2>>>(
        (const float*)p_xh, (const float*)p_Tx1, nullptr, Wc0, Wc1, bc, (float*)p_o1);

    // s = o1 + lrelu(mean@Wrel^T + xh@Wroot^T + brel)
    gemm_kernel<true, true, true><<<GB, TB, smem2>>>(
        (const float*)p_mean, (const float*)p_xh, (const float*)p_o1,
        Wrel, Wroot, brel, (float*)p_s);

    // o3 = s @ Wl^T + bl
    float* o3 = out + ((out_size >= 2 * NN * DD) ? (NN * DD) : 0);
    gemm_kernel<false, false, false><<<GB, TB, smem1>>>(
        (const float*)p_s, nullptr, nullptr, Wl, nullptr, bl, o3);

    // his = x
    if (out_size >= 2 * NN * DD)
        cudaMemcpyAsync(out, x, (size_t)NN * DD * sizeof(float),
                        cudaMemcpyDeviceToDevice);
}

// round 7
// speedup vs baseline: 2.1585x; 2.1585x over previous
#include <cuda_runtime.h>
#include <cuda_bf16.h>
#include <cstdint>

#define NN 50000
#define EE 800000
#define DD 128
#define MT 128
#define GTILES ((NN + MT - 1) / MT)     // 391
#define NB_SCAN ((NN + 511) / 512)      // 98
#define SPAD 136                         // bf16 elems per smem row (conflict-free)
#define TILE_ELEMS (128 * SPAD)          // 17408 bf16 per tile

// ---------------- scratch (device globals: allocation-free) ----------------
__device__ float g_xh[NN * DD];
__device__ float g_Tx1[NN * DD];
__device__ float g_mean[NN * DD];
__device__ float g_o1[NN * DD];
__device__ float g_s[NN * DD];
__device__ float g_deg[NN];
__device__ float g_dis[NN];
__device__ int   g_cnt[NN];
__device__ int   g_fill[NN];
__device__ int   g_rowptr[NN + 1];
__device__ int   g_bsum[128];
__device__ int   g_csrc[EE];
__device__ float g_cw[EE];

// ---------------- small kernels (CSR build) ----------------
__global__ void zero_kernel() {
    int i = blockIdx.x * blockDim.x + threadIdx.x;
    if (i < NN) { g_deg[i] = 0.f; g_cnt[i] = 0; g_fill[i] = 0; }
}
__global__ void hist_kernel(const int* __restrict__ ei, const float* __restrict__ ew) {
    int e = blockIdx.x * blockDim.x + threadIdx.x;
    if (e < EE) {
        atomicAdd(&g_deg[ei[e]], ew[e]);
        atomicAdd(&g_cnt[ei[EE + e]], 1);
    }
}
__global__ void dis_kernel() {
    int i = blockIdx.x * blockDim.x + threadIdx.x;
    if (i < NN) {
        float d = g_deg[i];
        g_dis[i] = (d > 0.f) ? rsqrtf(d) : 0.f;
    }
}
__global__ void scan1_kernel() {
    __shared__ int sm[512];
    int t = threadIdx.x, b = blockIdx.x;
    int i = b * 512 + t;
    int v = (i < NN) ? g_cnt[i] : 0;
    sm[t] = v;
    __syncthreads();
    #pragma unroll
    for (int off = 1; off < 512; off <<= 1) {
        int x = (t >= off) ? sm[t - off] : 0;
        __syncthreads();
        if (t >= off) sm[t] += x;
        __syncthreads();
    }
    if (i < NN) g_rowptr[i + 1] = sm[t];
    if (t == 511) g_bsum[b] = sm[511];
}
__global__ void scan2_kernel() {
    __shared__ int sm[128];
    int t = threadIdx.x;
    int v = (t < NB_SCAN) ? g_bsum[t] : 0;
    sm[t] = v;
    __syncthreads();
    #pragma unroll
    for (int off = 1; off < 128; off <<= 1) {
        int x = (t >= off) ? sm[t - off] : 0;
        __syncthreads();
        sm[t] += x;
        __syncthreads();
    }
    if (t < NB_SCAN) g_bsum[t] = sm[t] - v;
}
__global__ void scan3_kernel() {
    int i = blockIdx.x * blockDim.x + threadIdx.x;
    if (i < NN) {
        if (i == 0) g_rowptr[0] = 0;
        g_rowptr[i + 1] += g_bsum[i >> 9];
    }
}
__global__ void fill_kernel(const int* __restrict__ ei, const float* __restrict__ ew) {
    int e = blockIdx.x * blockDim.x + threadIdx.x;
    if (e < EE) {
        int d = ei[EE + e];
        int pos = g_rowptr[d] + atomicAdd(&g_fill[d], 1);
        g_csrc[pos] = ei[e];
        g_cw[pos]   = ew[e];
    }
}
__global__ void aggregate_kernel() {
    int warp = (blockIdx.x * blockDim.x + threadIdx.x) >> 5;
    int lane = threadIdx.x & 31;
    if (warp >= NN) return;
    int beg = g_rowptr[warp], end = g_rowptr[warp + 1];
    float dd = g_dis[warp];
    float4 aT = make_float4(0.f, 0.f, 0.f, 0.f);
    float4 aM = make_float4(0.f, 0.f, 0.f, 0.f);
    const float4* xh4 = (const float4*)g_xh;
    #pragma unroll 4
    for (int e = beg; e < end; ++e) {
        int s = g_csrc[e];
        float w = g_cw[e];
        float nrm = -g_dis[s] * w * dd;
        float4 v = xh4[s * 32 + lane];
        aT.x += nrm * v.x; aT.y += nrm * v.y; aT.z += nrm * v.z; aT.w += nrm * v.w;
        aM.x += w   * v.x; aM.y += w   * v.y; aM.z += w   * v.z; aM.w += w   * v.w;
    }
    ((float4*)g_Tx1)[warp * 32 + lane] = aT;
    float inv = 1.0f / fmaxf((float)g_cnt[warp], 1.0f);
    aM.x *= inv; aM.y *= inv; aM.z *= inv; aM.w *= inv;
    ((float4*)g_mean)[warp * 32 + lane] = aM;
}

// ---------------- mma.sync m16n8k16 bf16 (arch-portable HMMA path) ----------
__device__ __forceinline__ void mma16816(float* c, const uint32_t* a, const uint32_t* b) {
    asm volatile(
        "mma.sync.aligned.m16n8k16.row.col.f32.bf16.bf16.f32 "
        "{%0,%1,%2,%3}, {%4,%5,%6,%7}, {%8,%9}, {%0,%1,%2,%3};"
        : "+f"(c[0]), "+f"(c[1]), "+f"(c[2]), "+f"(c[3])
        : "r"(a[0]), "r"(a[1]), "r"(a[2]), "r"(a[3]), "r"(b[0]), "r"(b[1]));
}

// fp32 [128 x 128] chunk -> hi/lo bf16 row-major smem tiles (stride SPAD)
__device__ __forceinline__ void load_cvt(const float* __restrict__ src, int rowBase,
                                         int rowLim, __nv_bfloat16* hi,
                                         __nv_bfloat16* lo, int tid)
{
    const float4* s4 = (const float4*)src;
    #pragma unroll
    for (int it = 0; it < 16; ++it) {
        int idx = tid + it * 256;
        int r = idx >> 5, g = idx & 31;          // r: row 0..127, g: float4 col 0..31
        int gr = rowBase + r;
        float4 v = make_float4(0.f, 0.f, 0.f, 0.f);
        if (gr < rowLim) v = s4[gr * 32 + g];
        __nv_bfloat16 h0 = __float2bfloat16(v.x), h1 = __float2bfloat16(v.y);
        __nv_bfloat16 h2 = __float2bfloat16(v.z), h3 = __float2bfloat16(v.w);
        __nv_bfloat16 e0 = __float2bfloat16(v.x - __bfloat162float(h0));
        __nv_bfloat16 e1 = __float2bfloat16(v.y - __bfloat162float(h1));
        __nv_bfloat16 e2 = __float2bfloat16(v.z - __bfloat162float(h2));
        __nv_bfloat16 e3 = __float2bfloat16(v.w - __bfloat162float(h3));
        uint32_t hi01 = ((uint32_t)__bfloat16_as_ushort(h1) << 16) | __bfloat16_as_ushort(h0);
        uint32_t hi23 = ((uint32_t)__bfloat16_as_ushort(h3) << 16) | __bfloat16_as_ushort(h2);
        uint32_t lo01 = ((uint32_t)__bfloat16_as_ushort(e1) << 16) | __bfloat16_as_ushort(e0);
        uint32_t lo23 = ((uint32_t)__bfloat16_as_ushort(e3) << 16) | __bfloat16_as_ushort(e2);
        int eo = r * SPAD + g * 4;               // element offset (8B aligned)
        *(uint2*)(hi + eo) = make_uint2(hi01, hi23);
        *(uint2*)(lo + eo) = make_uint2(lo01, lo23);
    }
}

// One 128x128x128 product accumulated into acc (3-term bf16 hi/lo emulation)
__device__ __forceinline__ void compute_product(
    const __nv_bfloat16* __restrict__ Ahi, const __nv_bfloat16* __restrict__ Alo,
    const __nv_bfloat16* __restrict__ Whi, const __nv_bfloat16* __restrict__ Wlo,
    float acc[4][4][4], int mw, int nw, int lane)
{
    const int grp = lane >> 2, qp = lane & 3;
    #pragma unroll
    for (int ks = 0; ks < 8; ++ks) {
        const int kb = ks * 16 + qp * 2;
        uint32_t ah[4][4], al[4][4], wh[4][2], wl[4][2];
        #pragma unroll
        for (int i = 0; i < 4; ++i) {
            int eo = (mw * 64 + i * 16 + grp) * SPAD + kb;
            ah[i][0] = *(const uint32_t*)(Ahi + eo);
            ah[i][1] = *(const uint32_t*)(Ahi + eo + 8 * SPAD);
            ah[i][2] = *(const uint32_t*)(Ahi + eo + 8);
            ah[i][3] = *(const uint32_t*)(Ahi + eo + 8 * SPAD + 8);
            al[i][0] = *(const uint32_t*)(Alo + eo);
            al[i][1] = *(const uint32_t*)(Alo + eo + 8 * SPAD);
            al[i][2] = *(const uint32_t*)(Alo + eo + 8);
            al[i][3] = *(const uint32_t*)(Alo + eo + 8 * SPAD + 8);
        }
        #pragma unroll
        for (int j = 0; j < 4; ++j) {
            int eo = (nw * 32 + j * 8 + grp) * SPAD + kb;
            wh[j][0] = *(const uint32_t*)(Whi + eo);
            wh[j][1] = *(const uint32_t*)(Whi + eo + 8);
            wl[j][0] = *(const uint32_t*)(Wlo + eo);
            wl[j][1] = *(const uint32_t*)(Wlo + eo + 8);
        }
        #pragma unroll
        for (int i = 0; i < 4; ++i)
            #pragma unroll
            for (int j = 0; j < 4; ++j) {
                mma16816(acc[i][j], ah[i], wh[j]);
                mma16816(acc[i][j], al[i], wh[j]);
                mma16816(acc[i][j], ah[i], wl[j]);
            }
    }
}

// ---------------- tensor-core GEMM ----------------
// out = [ADDC? C +] [LEAKY? lrelu](A@W1^T [+ B@W2^T] + bias)
// CTA: 128x128 tile, 256 threads = 8 warps (2 x 4); warp tile 64x32.
template <bool DUAL, bool LEAKY, bool ADDC>
__global__ void __launch_bounds__(256, 1)
gemm_mma(const float* __restrict__ A, const float* __restrict__ B,
         const float* __restrict__ C,
         const float* __restrict__ W1, const float* __restrict__ W2,
         const float* __restrict__ bias, float* __restrict__ out)
{
    extern __shared__ __align__(16) __nv_bfloat16 smem[];
    __nv_bfloat16* Ahi = smem;
    __nv_bfloat16* Alo = Ahi + TILE_ELEMS;
    __nv_bfloat16* Whi = Alo + TILE_ELEMS;
    __nv_bfloat16* Wlo = Whi + TILE_ELEMS;

    const int tid = threadIdx.x, wid = tid >> 5, lane = tid & 31;
    const int mw = wid >> 2, nw = wid & 3;
    const int rowBase = blockIdx.x * MT;

    float acc[4][4][4];
    #pragma unroll
    for (int i = 0; i < 4; ++i)
        #pragma unroll
        for (int j = 0; j < 4; ++j)
            #pragma unroll
            for (int q = 0; q < 4; ++q) acc[i][j][q] = 0.f;

    // product 1: A @ W1^T
    load_cvt(A, rowBase, NN, Ahi, Alo, tid);
    load_cvt(W1, 0, DD, Whi, Wlo, tid);
    __syncthreads();
    compute_product(Ahi, Alo, Whi, Wlo, acc, mw, nw, lane);

    if (DUAL) {   // product 2: B @ W2^T (reuse smem)
        __syncthreads();
        load_cvt(B, rowBase, NN, Ahi, Alo, tid);
        load_cvt(W2, 0, DD, Whi, Wlo, tid);
        __syncthreads();
        compute_product(Ahi, Alo, Whi, Wlo, acc, mw, nw, lane);
    }

    // epilogue: bias + (leaky) + (addC) + store
    const int grp = lane >> 2, qp = lane & 3;
    #pragma unroll
    for (int i = 0; i < 4; ++i) {
        int r0 = rowBase + mw * 64 + i * 16 + grp;
        int r1 = r0 + 8;
        #pragma unroll
        for (int j = 0; j < 4; ++j) {
            int col = nw * 32 + j * 8 + qp * 2;
            float2 bb = *(const float2*)(bias + col);
            float v0 = acc[i][j][0] + bb.x, v1 = acc[i][j][1] + bb.y;
            float v2 = acc[i][j][2] + bb.x, v3 = acc[i][j][3] + bb.y;
            if (LEAKY) {
                v0 = (v0 > 0.f) ? v0 : 0.01f * v0;
                v1 = (v1 > 0.f) ? v1 : 0.01f * v1;
                v2 = (v2 > 0.f) ? v2 : 0.01f * v2;
                v3 = (v3 > 0.f) ? v3 : 0.01f * v3;
            }
            if (r0 < NN) {
                float2 o0 = make_float2(v0, v1);
                if (ADDC) {
                    float2 cc = *(const float2*)(C + r0 * DD + col);
                    o0.x += cc.x; o0.y += cc.y;
                }
                *(float2*)(out + r0 * DD + col) = o0;
            }
            if (r1 < NN) {
                float2 o1 = make_float2(v2, v3);
                if (ADDC) {
                    float2 cc = *(const float2*)(C + r1 * DD + col);
                    o1.x += cc.x; o1.y += cc.y;
                }
                *(float2*)(out + r1 * DD + col) = o1;
            }
        }
    }
}

// ---------------- launch ----------------
extern "C" void kernel_launch(void* const* d_in, const int* in_sizes, int n_in,
                              void* d_out, int out_size)
{
    (void)in_sizes; (void)n_in;
    const float* x    = (const float*)d_in[1];
    const int*   ei   = (const int*)  d_in[2];
    const float* ew   = (const float*)d_in[3];
    const float* Wp   = (const float*)d_in[4];
    const float* bp   = (const float*)d_in[5];
    const float* Wc0  = (const float*)d_in[6];
    const float* Wc1  = (const float*)d_in[7];
    const float* bc   = (const float*)d_in[8];
    const float* Wrel = (const float*)d_in[9];
    const float* brel = (const float*)d_in[10];
    const float* Wroot= (const float*)d_in[11];
    const float* Wl   = (const float*)d_in[12];
    const float* bl   = (const float*)d_in[13];
    float* out = (float*)d_out;

    void *p_xh, *p_Tx1, *p_mean, *p_o1, *p_s;
    cudaGetSymbolAddress(&p_xh,   g_xh);
    cudaGetSymbolAddress(&p_Tx1,  g_Tx1);
    cudaGetSymbolAddress(&p_mean, g_mean);
    cudaGetSymbolAddress(&p_o1,   g_o1);
    cudaGetSymbolAddress(&p_s,    g_s);

    const int smemB = 4 * TILE_ELEMS * (int)sizeof(__nv_bfloat16);   // 139264 B
    cudaFuncSetAttribute(gemm_mma<false, false, false>,
                         cudaFuncAttributeMaxDynamicSharedMemorySize, smemB);
    cudaFuncSetAttribute(gemm_mma<true, true, false>,
                         cudaFuncAttributeMaxDynamicSharedMemorySize, smemB);
    cudaFuncSetAttribute(gemm_mma<true, true, true>,
                         cudaFuncAttributeMaxDynamicSharedMemorySize, smemB);

    const int TB = 256;
    zero_kernel<<<(NN + TB - 1) / TB, TB>>>();
    hist_kernel<<<(EE + TB - 1) / TB, TB>>>(ei, ew);
    dis_kernel<<<(NN + TB - 1) / TB, TB>>>();
    scan1_kernel<<<NB_SCAN, 512>>>();
    scan2_kernel<<<1, 128>>>();
    scan3_kernel<<<(NN + TB - 1) / TB, TB>>>();
    fill_kernel<<<(EE + TB - 1) / TB, TB>>>(ei, ew);

    // xh = x @ Wp^T + bp
    gemm_mma<false, false, false><<<GTILES, TB, smemB>>>(
        x, nullptr, nullptr, Wp, nullptr, bp, (float*)p_xh);

    // Tx1 + mean (CSR gather)
    aggregate_kernel<<<(NN * 32 + TB - 1) / TB, TB>>>();

    // o1 = lrelu(xh@Wc0^T + Tx1@Wc1^T + bc)
    gemm_mma<true, true, false><<<GTILES, TB, smemB>>>(
        (const float*)p_xh, (const float*)p_Tx1, nullptr, Wc0, Wc1, bc, (float*)p_o1);

    // s = o1 + lrelu(mean@Wrel^T + xh@Wroot^T + brel)
    gemm_mma<true, true, true><<<GTILES, TB, smemB>>>(
        (const float*)p_mean, (const float*)p_xh, (const float*)p_o1,
        Wrel, Wroot, brel, (float*)p_s);

    // o3 = s @ Wl^T + bl
    float* o3 = out + ((out_size >= 2 * NN * DD) ? (NN * DD) : 0);
    gemm_mma<false, false, false><<<GTILES, TB, smemB>>>(
        (const float*)p_s, nullptr, nullptr, Wl, nullptr, bl, o3);

    // his = x
    if (out_size >= 2 * NN * DD)
        cudaMemcpyAsync(out, x, (size_t)NN * DD * sizeof(float),
                        cudaMemcpyDeviceToDevice);
}

// round 9
// speedup vs baseline: 2.3100x; 1.0702x over previous
#include <cuda_runtime.h>
#include <cuda_bf16.h>
#include <cstdint>

#define NN 50000
#define EE 800000
#define DD 128
#define MT 128
#define GTILES ((NN + MT - 1) / MT)     // 391
#define NB_SCAN ((NN + 511) / 512)      // 98
#define SPAD 136                         // bf16 elems per smem row (conflict-free)
#define TILE_ELEMS (128 * SPAD)          // 17408 bf16 per tile

// ---------------- scratch (device globals: allocation-free) ----------------
__device__ float g_xh[NN * DD];
__device__ float g_Tx1[NN * DD];
__device__ float g_mean[NN * DD];
__device__ float g_deg[NN];
__device__ float g_dis[NN];
__device__ int   g_cnt[NN];
__device__ int   g_fill[NN];
__device__ int   g_rowptr[NN + 1];
__device__ int   g_bsum[128];
__device__ int   g_csrc[EE];
__device__ float g_cw[EE];

// ---------------- small kernels (CSR build) ----------------
__global__ void zero_kernel() {
    int i = blockIdx.x * blockDim.x + threadIdx.x;
    if (i < NN) { g_deg[i] = 0.f; g_cnt[i] = 0; g_fill[i] = 0; }
}
__global__ void hist_kernel(const int* __restrict__ ei, const float* __restrict__ ew) {
    int e = blockIdx.x * blockDim.x + threadIdx.x;
    if (e < EE) {
        atomicAdd(&g_deg[ei[e]], ew[e]);
        atomicAdd(&g_cnt[ei[EE + e]], 1);
    }
}
__global__ void dis_kernel() {
    int i = blockIdx.x * blockDim.x + threadIdx.x;
    if (i < NN) {
        float d = g_deg[i];
        g_dis[i] = (d > 0.f) ? rsqrtf(d) : 0.f;
    }
}
__global__ void scan1_kernel() {
    __shared__ int sm[512];
    int t = threadIdx.x, b = blockIdx.x;
    int i = b * 512 + t;
    int v = (i < NN) ? g_cnt[i] : 0;
    sm[t] = v;
    __syncthreads();
    #pragma unroll
    for (int off = 1; off < 512; off <<= 1) {
        int x = (t >= off) ? sm[t - off] : 0;
        __syncthreads();
        if (t >= off) sm[t] += x;
        __syncthreads();
    }
    if (i < NN) g_rowptr[i + 1] = sm[t];
    if (t == 511) g_bsum[b] = sm[511];
}
__global__ void scan2_kernel() {
    __shared__ int sm[128];
    int t = threadIdx.x;
    int v = (t < NB_SCAN) ? g_bsum[t] : 0;
    sm[t] = v;
    __syncthreads();
    #pragma unroll
    for (int off = 1; off < 128; off <<= 1) {
        int x = (t >= off) ? sm[t - off] : 0;
        __syncthreads();
        sm[t] += x;
        __syncthreads();
    }
    if (t < NB_SCAN) g_bsum[t] = sm[t] - v;
}
__global__ void scan3_kernel() {
    int i = blockIdx.x * blockDim.x + threadIdx.x;
    if (i < NN) {
        if (i == 0) g_rowptr[0] = 0;
        g_rowptr[i + 1] += g_bsum[i >> 9];
    }
}
__global__ void fill_kernel(const int* __restrict__ ei, const float* __restrict__ ew) {
    int e = blockIdx.x * blockDim.x + threadIdx.x;
    if (e < EE) {
        int d = ei[EE + e];
        int pos = g_rowptr[d] + atomicAdd(&g_fill[d], 1);
        g_csrc[pos] = ei[e];
        g_cw[pos]   = ew[e];
    }
}
__global__ void aggregate_kernel() {
    int warp = (blockIdx.x * blockDim.x + threadIdx.x) >> 5;
    int lane = threadIdx.x & 31;
    if (warp >= NN) return;
    int beg = g_rowptr[warp], end = g_rowptr[warp + 1];
    float dd = g_dis[warp];
    float4 aT = make_float4(0.f, 0.f, 0.f, 0.f);
    float4 aM = make_float4(0.f, 0.f, 0.f, 0.f);
    const float4* xh4 = (const float4*)g_xh;
    #pragma unroll 4
    for (int e = beg; e < end; ++e) {
        int s = g_csrc[e];
        float w = g_cw[e];
        float nrm = -g_dis[s] * w * dd;
        float4 v = xh4[s * 32 + lane];
        aT.x += nrm * v.x; aT.y += nrm * v.y; aT.z += nrm * v.z; aT.w += nrm * v.w;
        aM.x += w   * v.x; aM.y += w   * v.y; aM.z += w   * v.z; aM.w += w   * v.w;
    }
    ((float4*)g_Tx1)[warp * 32 + lane] = aT;
    float inv = 1.0f / fmaxf((float)g_cnt[warp], 1.0f);
    aM.x *= inv; aM.y *= inv; aM.z *= inv; aM.w *= inv;
    ((float4*)g_mean)[warp * 32 + lane] = aM;
}

// ---------------- mma.sync m16n8k16 bf16 ----------------
__device__ __forceinline__ void mma16816(float* c, const uint32_t* a, const uint32_t* b) {
    asm volatile(
        "mma.sync.aligned.m16n8k16.row.col.f32.bf16.bf16.f32 "
        "{%0,%1,%2,%3}, {%4,%5,%6,%7}, {%8,%9}, {%0,%1,%2,%3};"
        : "+f"(c[0]), "+f"(c[1]), "+f"(c[2]), "+f"(c[3])
        : "r"(a[0]), "r"(a[1]), "r"(a[2]), "r"(a[3]), "r"(b[0]), "r"(b[1]));
}

__device__ __forceinline__ uint32_t pack_hi(float a, float b) {
    __nv_bfloat16 x = __float2bfloat16(a), y = __float2bfloat16(b);
    return ((uint32_t)__bfloat16_as_ushort(y) << 16) | __bfloat16_as_ushort(x);
}

// fp32 [128 x 128] chunk -> hi/lo bf16 row-major smem tiles (stride SPAD)
__device__ __forceinline__ void load_cvt(const float* __restrict__ src, int rowBase,
                                         int rowLim, __nv_bfloat16* hi,
                                         __nv_bfloat16* lo, int tid)
{
    const float4* s4 = (const float4*)src;
    #pragma unroll
    for (int it = 0; it < 16; ++it) {
        int idx = tid + it * 256;
        int r = idx >> 5, g = idx & 31;
        int gr = rowBase + r;
        float4 v = make_float4(0.f, 0.f, 0.f, 0.f);
        if (gr < rowLim) v = s4[gr * 32 + g];
        __nv_bfloat16 h0 = __float2bfloat16(v.x), h1 = __float2bfloat16(v.y);
        __nv_bfloat16 h2 = __float2bfloat16(v.z), h3 = __float2bfloat16(v.w);
        __nv_bfloat16 e0 = __float2bfloat16(v.x - __bfloat162float(h0));
        __nv_bfloat16 e1 = __float2bfloat16(v.y - __bfloat162float(h1));
        __nv_bfloat16 e2 = __float2bfloat16(v.z - __bfloat162float(h2));
        __nv_bfloat16 e3 = __float2bfloat16(v.w - __bfloat162float(h3));
        uint32_t hi01 = ((uint32_t)__bfloat16_as_ushort(h1) << 16) | __bfloat16_as_ushort(h0);
        uint32_t hi23 = ((uint32_t)__bfloat16_as_ushort(h3) << 16) | __bfloat16_as_ushort(h2);
        uint32_t lo01 = ((uint32_t)__bfloat16_as_ushort(e1) << 16) | __bfloat16_as_ushort(e0);
        uint32_t lo23 = ((uint32_t)__bfloat16_as_ushort(e3) << 16) | __bfloat16_as_ushort(e2);
        int eo = r * SPAD + g * 4;
        *(uint2*)(hi + eo) = make_uint2(hi01, hi23);
        *(uint2*)(lo + eo) = make_uint2(lo01, lo23);
    }
}

// One 128x128x128 product accumulated into acc (3-term bf16 hi/lo emulation)
__device__ __forceinline__ void compute_product(
    const __nv_bfloat16* __restrict__ Ahi, const __nv_bfloat16* __restrict__ Alo,
    const __nv_bfloat16* __restrict__ Whi, const __nv_bfloat16* __restrict__ Wlo,
    float acc[4][4][4], int mw, int nw, int lane)
{
    const int grp = lane >> 2, qp = lane & 3;
    #pragma unroll
    for (int ks = 0; ks < 8; ++ks) {
        const int kb = ks * 16 + qp * 2;
        uint32_t ah[4][4], al[4][4], wh[4][2], wl[4][2];
        #pragma unroll
        for (int i = 0; i < 4; ++i) {
            int eo = (mw * 64 + i * 16 + grp) * SPAD + kb;
            ah[i][0] = *(const uint32_t*)(Ahi + eo);
            ah[i][1] = *(const uint32_t*)(Ahi + eo + 8 * SPAD);
            ah[i][2] = *(const uint32_t*)(Ahi + eo + 8);
            ah[i][3] = *(const uint32_t*)(Ahi + eo + 8 * SPAD + 8);
            al[i][0] = *(const uint32_t*)(Alo + eo);
            al[i][1] = *(const uint32_t*)(Alo + eo + 8 * SPAD);
            al[i][2] = *(const uint32_t*)(Alo + eo + 8);
            al[i][3] = *(const uint32_t*)(Alo + eo + 8 * SPAD + 8);
        }
        #pragma unroll
        for (int j = 0; j < 4; ++j) {
            int eo = (nw * 32 + j * 8 + grp) * SPAD + kb;
            wh[j][0] = *(const uint32_t*)(Whi + eo);
            wh[j][1] = *(const uint32_t*)(Whi + eo + 8);
            wl[j][0] = *(const uint32_t*)(Wlo + eo);
            wl[j][1] = *(const uint32_t*)(Wlo + eo + 8);
        }
        #pragma unroll
        for (int i = 0; i < 4; ++i)
            #pragma unroll
            for (int j = 0; j < 4; ++j) {
                mma16816(acc[i][j], ah[i], wh[j]);
                mma16816(acc[i][j], al[i], wh[j]);
                mma16816(acc[i][j], ah[i], wl[j]);
            }
    }
}

#define ZERO_ACC(a) do {                                       \
    _Pragma("unroll") for (int i = 0; i < 4; ++i)              \
    _Pragma("unroll") for (int j = 0; j < 4; ++j)              \
    _Pragma("unroll") for (int q = 0; q < 4; ++q) (a)[i][j][q] = 0.f; } while (0)

// ---------------- single-product GEMM (xh = x @ Wp^T + bp) ----------------
__global__ void __launch_bounds__(256, 1)
gemm_one(const float* __restrict__ A, const float* __restrict__ W1,
         const float* __restrict__ bias, float* __restrict__ out)
{
    extern __shared__ __align__(16) __nv_bfloat16 smem[];
    __nv_bfloat16* Ahi = smem;
    __nv_bfloat16* Alo = Ahi + TILE_ELEMS;
    __nv_bfloat16* Whi = Alo + TILE_ELEMS;
    __nv_bfloat16* Wlo = Whi + TILE_ELEMS;

    const int tid = threadIdx.x, wid = tid >> 5, lane = tid & 31;
    const int mw = wid >> 2, nw = wid & 3;
    const int rowBase = blockIdx.x * MT;

    float acc[4][4][4];
    ZERO_ACC(acc);

    load_cvt(A, rowBase, NN, Ahi, Alo, tid);
    load_cvt(W1, 0, DD, Whi, Wlo, tid);
    __syncthreads();
    compute_product(Ahi, Alo, Whi, Wlo, acc, mw, nw, lane);

    const int grp = lane >> 2, qp = lane & 3;
    #pragma unroll
    for (int i = 0; i < 4; ++i) {
        int r0 = rowBase + mw * 64 + i * 16 + grp;
        #pragma unroll
        for (int j = 0; j < 4; ++j) {
            int col = nw * 32 + j * 8 + qp * 2;
            float2 bb = *(const float2*)(bias + col);
            if (r0 < NN)
                *(float2*)(out + r0 * DD + col) =
                    make_float2(acc[i][j][0] + bb.x, acc[i][j][1] + bb.y);
            if (r0 + 8 < NN)
                *(float2*)(out + (r0 + 8) * DD + col) =
                    make_float2(acc[i][j][2] + bb.x, acc[i][j][3] + bb.y);
        }
    }
}

// ---------------- mega kernel: o1, o2, s, o3 fused ----------------
// o1 = lrelu(xh@Wc0^T + Tx1@Wc1^T + bc)            (kept in registers)
// o2 = lrelu(mean@Wrel^T + xh@Wroot^T + brel)
// s  = o1 + o2   (converted to bf16 hi/lo in smem)
// o3 = s@Wl^T + bl                                  (written to output)
__global__ void __launch_bounds__(256, 1)
gemm_mega(const float* __restrict__ Wc0, const float* __restrict__ Wc1,
          const float* __restrict__ bc,
          const float* __restrict__ Wrel, const float* __restrict__ brel,
          const float* __restrict__ Wroot,
          const float* __restrict__ Wl, const float* __restrict__ bl,
          float* __restrict__ out)
{
    extern __shared__ __align__(16) __nv_bfloat16 smem[];
    __nv_bfloat16* Ahi = smem;
    __nv_bfloat16* Alo = Ahi + TILE_ELEMS;
    __nv_bfloat16* Whi = Alo + TILE_ELEMS;
    __nv_bfloat16* Wlo = Whi + TILE_ELEMS;

    const int tid = threadIdx.x, wid = tid >> 5, lane = tid & 31;
    const int mw = wid >> 2, nw = wid & 3;
    const int grp = lane >> 2, qp = lane & 3;
    const int rowBase = blockIdx.x * MT;

    float acc[4][4][4], o1r[4][4][4];
    ZERO_ACC(acc);

    // P1: Tx1 @ Wc1
    load_cvt(g_Tx1, rowBase, NN, Ahi, Alo, tid);
    load_cvt(Wc1, 0, DD, Whi, Wlo, tid);
    __syncthreads();
    compute_product(Ahi, Alo, Whi, Wlo, acc, mw, nw, lane);
    __syncthreads();

    // P2: xh @ Wc0  (A <- xh, W <- Wc0)
    load_cvt(g_xh, rowBase, NN, Ahi, Alo, tid);
    load_cvt(Wc0, 0, DD, Whi, Wlo, tid);
    __syncthreads();
    compute_product(Ahi, Alo, Whi, Wlo, acc, mw, nw, lane);

    // epilogue 1: o1 in registers
    #pragma unroll
    for (int i = 0; i < 4; ++i)
        #pragma unroll
        for (int j = 0; j < 4; ++j) {
            int col = nw * 32 + j * 8 + qp * 2;
            float2 bb = *(const float2*)(bc + col);
            float v0 = acc[i][j][0] + bb.x, v1 = acc[i][j][1] + bb.y;
            float v2 = acc[i][j][2] + bb.x, v3 = acc[i][j][3] + bb.y;
            o1r[i][j][0] = (v0 > 0.f) ? v0 : 0.01f * v0;
            o1r[i][j][1] = (v1 > 0.f) ? v1 : 0.01f * v1;
            o1r[i][j][2] = (v2 > 0.f) ? v2 : 0.01f * v2;
            o1r[i][j][3] = (v3 > 0.f) ? v3 : 0.01f * v3;
        }
    ZERO_ACC(acc);
    __syncthreads();

    // P3: xh @ Wroot  (A tile still holds xh; only reload W)
    load_cvt(Wroot, 0, DD, Whi, Wlo, tid);
    __syncthreads();
    compute_product(Ahi, Alo, Whi, Wlo, acc, mw, nw, lane);
    __syncthreads();

    // P4: mean @ Wrel
    load_cvt(g_mean, rowBase, NN, Ahi, Alo, tid);
    load_cvt(Wrel, 0, DD, Whi, Wlo, tid);
    __syncthreads();
    compute_product(Ahi, Alo, Whi, Wlo, acc, mw, nw, lane);
    __syncthreads();   // all A reads done before s overwrites A tiles

    // epilogue 2: s = o1 + lrelu(acc + brel); write s (bf16 hi/lo) into A tiles
    #pragma unroll
    for (int i = 0; i < 4; ++i) {
        int lr0 = mw * 64 + i * 16 + grp;
        #pragma unroll
        for (int j = 0; j < 4; ++j) {
            int col = nw * 32 + j * 8 + qp * 2;
            float2 bb = *(const float2*)(brel + col);
            float v0 = acc[i][j][0] + bb.x, v1 = acc[i][j][1] + bb.y;
            float v2 = acc[i][j][2] + bb.x, v3 = acc[i][j][3] + bb.y;
            v0 = (v0 > 0.f) ? v0 : 0.01f * v0;
            v1 = (v1 > 0.f) ? v1 : 0.01f * v1;
            v2 = (v2 > 0.f) ? v2 : 0.01f * v2;
            v3 = (v3 > 0.f) ? v3 : 0.01f * v3;
            float s0 = o1r[i][j][0] + v0, s1 = o1r[i][j][1] + v1;
            float s2 = o1r[i][j][2] + v2, s3 = o1r[i][j][3] + v3;
            // hi parts
            uint32_t h01 = pack_hi(s0, s1);
            uint32_t h23 = pack_hi(s2, s3);
            __nv_bfloat16 h0 = __float2bfloat16(s0), h1 = __float2bfloat16(s1);
            __nv_bfloat16 h2 = __float2bfloat16(s2), h3 = __float2bfloat16(s3);
            uint32_t l01 = pack_hi(s0 - __bfloat162float(h0), s1 - __bfloat162float(h1));
            uint32_t l23 = pack_hi(s2 - __bfloat162float(h2), s3 - __bfloat162float(h3));
            int eo0 = lr0 * SPAD + col;
            int eo1 = (lr0 + 8) * SPAD + col;
            *(uint32_t*)(Ahi + eo0) = h01;
            *(uint32_t*)(Alo + eo0) = l01;
            *(uint32_t*)(Ahi + eo1) = h23;
            *(uint32_t*)(Alo + eo1) = l23;
        }
    }
    ZERO_ACC(acc);
    // P5: load Wl, compute s @ Wl
    load_cvt(Wl, 0, DD, Whi, Wlo, tid);
    __syncthreads();
    compute_product(Ahi, Alo, Whi, Wlo, acc, mw, nw, lane);

    // epilogue 3: o3 = acc + bl -> out
    #pragma unroll
    for (int i = 0; i < 4; ++i) {
        int r0 = rowBase + mw * 64 + i * 16 + grp;
        #pragma unroll
        for (int j = 0; j < 4; ++j) {
            int col = nw * 32 + j * 8 + qp * 2;
            float2 bb = *(const float2*)(bl + col);
            if (r0 < NN)
                *(float2*)(out + r0 * DD + col) =
                    make_float2(acc[i][j][0] + bb.x, acc[i][j][1] + bb.y);
            if (r0 + 8 < NN)
                *(float2*)(out + (r0 + 8) * DD + col) =
                    make_float2(acc[i][j][2] + bb.x, acc[i][j][3] + bb.y);
        }
    }
}

// ---------------- launch ----------------
extern "C" void kernel_launch(void* const* d_in, const int* in_sizes, int n_in,
                              void* d_out, int out_size)
{
    (void)in_sizes; (void)n_in;
    const float* x    = (const float*)d_in[1];
    const int*   ei   = (const int*)  d_in[2];
    const float* ew   = (const float*)d_in[3];
    const float* Wp   = (const float*)d_in[4];
    const float* bp   = (const float*)d_in[5];
    const float* Wc0  = (const float*)d_in[6];
    const float* Wc1  = (const float*)d_in[7];
    const float* bc   = (const float*)d_in[8];
    const float* Wrel = (const float*)d_in[9];
    const float* brel = (const float*)d_in[10];
    const float* Wroot= (const float*)d_in[11];
    const float* Wl   = (const float*)d_in[12];
    const float* bl   = (const float*)d_in[13];
    float* out = (float*)d_out;

    void* p_xh;
    cudaGetSymbolAddress(&p_xh, g_xh);

    // lazily created once (first call = uncaptured correctness run)
    static cudaStream_t s2 = nullptr;
    static cudaEvent_t ev1 = nullptr, ev2 = nullptr;
    static bool attrDone = false;
    const int smemB = 4 * TILE_ELEMS * (int)sizeof(__nv_bfloat16);   // 139264 B
    if (!s2) {
        cudaStreamCreateWithFlags(&s2, cudaStreamNonBlocking);
        cudaEventCreateWithFlags(&ev1, cudaEventDisableTiming);
        cudaEventCreateWithFlags(&ev2, cudaEventDisableTiming);
    }
    if (!attrDone) {
        cudaFuncSetAttribute(gemm_one,
                             cudaFuncAttributeMaxDynamicSharedMemorySize, smemB);
        cudaFuncSetAttribute(gemm_mega,
                             cudaFuncAttributeMaxDynamicSharedMemorySize, smemB);
        attrDone = true;
    }

    const int TB = 256;

    // ---- fork: CSR build + his-copy on s2, xh GEMM on main stream ----
    cudaEventRecord(ev1, 0);
    cudaStreamWaitEvent(s2, ev1, 0);

    if (out_size >= 2 * NN * DD)
        cudaMemcpyAsync(out, x, (size_t)NN * DD * sizeof(float),
                        cudaMemcpyDeviceToDevice, s2);
    zero_kernel<<<(NN + TB - 1) / TB, TB, 0, s2>>>();
    hist_kernel<<<(EE + TB - 1) / TB, TB, 0, s2>>>(ei, ew);
    dis_kernel<<<(NN + TB - 1) / TB, TB, 0, s2>>>();
    scan1_kernel<<<NB_SCAN, 512, 0, s2>>>();
    scan2_kernel<<<1, 128, 0, s2>>>();
    scan3_kernel<<<(NN + TB - 1) / TB, TB, 0, s2>>>();
    fill_kernel<<<(EE + TB - 1) / TB, TB, 0, s2>>>(ei, ew);

    // main stream: xh = x @ Wp^T + bp
    gemm_one<<<GTILES, TB, smemB>>>(x, Wp, bp, (float*)p_xh);

    // ---- join ----
    cudaEventRecord(ev2, s2);
    cudaStreamWaitEvent(0, ev2, 0);

    // Tx1 + mean (CSR gather)
    aggregate_kernel<<<(NN * 32 + TB - 1) / TB, TB>>>();

    // fused o1 / o2 / s / o3
    float* o3 = out + ((out_size >= 2 * NN * DD) ? (NN * DD) : 0);
    gemm_mega<<<GTILES, TB, smemB>>>(Wc0, Wc1, bc, Wrel, brel, Wroot, Wl, bl, o3);
}

// round 10
// speedup vs baseline: 2.3116x; 1.0007x over previous
#include <cuda_runtime.h>
#include <cuda_bf16.h>
#include <cstdint>

#define NN 50000
#define EE 800000
#define DD 128
#define MT 128
#define GTILES ((NN + MT - 1) / MT)     // 391
#define NB_SCAN ((NN + 511) / 512)      // 98
#define SPAD 136                         // bf16 elems per smem row (conflict-free)
#define TILE_ELEMS (128 * SPAD)          // 17408 bf16 per tile

// ---------------- scratch (device globals: allocation-free) ----------------
__device__ float g_xh[NN * DD];
__device__ float g_Tx1[NN * DD];
__device__ float g_mean[NN * DD];
__device__ float g_p1[NN * DD];          // xh @ Wc0^T   (raw partial)
__device__ float g_p2[NN * DD];          // xh @ Wroot^T (raw partial)
__device__ float g_deg[NN];
__device__ float g_dis[NN];
__device__ int   g_cnt[NN];
__device__ int   g_fill[NN];
__device__ int   g_rowptr[NN + 1];
__device__ int   g_bsum[128];
__device__ int   g_csrc[EE];
__device__ float g_cw[EE];

// ---------------- small kernels (CSR build) ----------------
__global__ void zero_kernel() {
    int i = blockIdx.x * blockDim.x + threadIdx.x;
    if (i < NN) { g_deg[i] = 0.f; g_cnt[i] = 0; g_fill[i] = 0; }
}
__global__ void hist_kernel(const int* __restrict__ ei, const float* __restrict__ ew) {
    int e = blockIdx.x * blockDim.x + threadIdx.x;
    if (e < EE) {
        atomicAdd(&g_deg[ei[e]], ew[e]);
        atomicAdd(&g_cnt[ei[EE + e]], 1);
    }
}
__global__ void dis_kernel() {
    int i = blockIdx.x * blockDim.x + threadIdx.x;
    if (i < NN) {
        float d = g_deg[i];
        g_dis[i] = (d > 0.f) ? rsqrtf(d) : 0.f;
    }
}
__global__ void scan1_kernel() {
    __shared__ int sm[512];
    int t = threadIdx.x, b = blockIdx.x;
    int i = b * 512 + t;
    int v = (i < NN) ? g_cnt[i] : 0;
    sm[t] = v;
    __syncthreads();
    #pragma unroll
    for (int off = 1; off < 512; off <<= 1) {
        int x = (t >= off) ? sm[t - off] : 0;
        __syncthreads();
        if (t >= off) sm[t] += x;
        __syncthreads();
    }
    if (i < NN) g_rowptr[i + 1] = sm[t];
    if (t == 511) g_bsum[b] = sm[511];
}
__global__ void scan2_kernel() {
    __shared__ int sm[128];
    int t = threadIdx.x;
    int v = (t < NB_SCAN) ? g_bsum[t] : 0;
    sm[t] = v;
    __syncthreads();
    #pragma unroll
    for (int off = 1; off < 128; off <<= 1) {
        int x = (t >= off) ? sm[t - off] : 0;
        __syncthreads();
        sm[t] += x;
        __syncthreads();
    }
    if (t < NB_SCAN) g_bsum[t] = sm[t] - v;
}
__global__ void scan3_kernel() {
    int i = blockIdx.x * blockDim.x + threadIdx.x;
    if (i < NN) {
        if (i == 0) g_rowptr[0] = 0;
        g_rowptr[i + 1] += g_bsum[i >> 9];
    }
}
__global__ void fill_kernel(const int* __restrict__ ei, const float* __restrict__ ew) {
    int e = blockIdx.x * blockDim.x + threadIdx.x;
    if (e < EE) {
        int d = ei[EE + e];
        int pos = g_rowptr[d] + atomicAdd(&g_fill[d], 1);
        g_csrc[pos] = ei[e];
        g_cw[pos]   = ew[e];
    }
}
__global__ void aggregate_kernel() {
    int warp = (blockIdx.x * blockDim.x + threadIdx.x) >> 5;
    int lane = threadIdx.x & 31;
    if (warp >= NN) return;
    int beg = g_rowptr[warp], end = g_rowptr[warp + 1];
    float dd = g_dis[warp];
    float4 aT = make_float4(0.f, 0.f, 0.f, 0.f);
    float4 aM = make_float4(0.f, 0.f, 0.f, 0.f);
    const float4* xh4 = (const float4*)g_xh;
    #pragma unroll 4
    for (int e = beg; e < end; ++e) {
        int s = g_csrc[e];
        float w = g_cw[e];
        float nrm = -g_dis[s] * w * dd;
        float4 v = xh4[s * 32 + lane];
        aT.x += nrm * v.x; aT.y += nrm * v.y; aT.z += nrm * v.z; aT.w += nrm * v.w;
        aM.x += w   * v.x; aM.y += w   * v.y; aM.z += w   * v.z; aM.w += w   * v.w;
    }
    ((float4*)g_Tx1)[warp * 32 + lane] = aT;
    float inv = 1.0f / fmaxf((float)g_cnt[warp], 1.0f);
    aM.x *= inv; aM.y *= inv; aM.z *= inv; aM.w *= inv;
    ((float4*)g_mean)[warp * 32 + lane] = aM;
}

// ---------------- mma.sync m16n8k16 bf16 ----------------
__device__ __forceinline__ void mma16816(float* c, const uint32_t* a, const uint32_t* b) {
    asm volatile(
        "mma.sync.aligned.m16n8k16.row.col.f32.bf16.bf16.f32 "
        "{%0,%1,%2,%3}, {%4,%5,%6,%7}, {%8,%9}, {%0,%1,%2,%3};"
        : "+f"(c[0]), "+f"(c[1]), "+f"(c[2]), "+f"(c[3])
        : "r"(a[0]), "r"(a[1]), "r"(a[2]), "r"(a[3]), "r"(b[0]), "r"(b[1]));
}

__device__ __forceinline__ uint32_t pack_hi(float a, float b) {
    __nv_bfloat16 x = __float2bfloat16(a), y = __float2bfloat16(b);
    return ((uint32_t)__bfloat16_as_ushort(y) << 16) | __bfloat16_as_ushort(x);
}

// fp32 [128 x 128] chunk -> hi/lo bf16 row-major smem tiles (stride SPAD)
__device__ __forceinline__ void load_cvt(const float* __restrict__ src, int rowBase,
                                         int rowLim, __nv_bfloat16* hi,
                                         __nv_bfloat16* lo, int tid)
{
    const float4* s4 = (const float4*)src;
    #pragma unroll
    for (int it = 0; it < 16; ++it) {
        int idx = tid + it * 256;
        int r = idx >> 5, g = idx & 31;
        int gr = rowBase + r;
        float4 v = make_float4(0.f, 0.f, 0.f, 0.f);
        if (gr < rowLim) v = s4[gr * 32 + g];
        __nv_bfloat16 h0 = __float2bfloat16(v.x), h1 = __float2bfloat16(v.y);
        __nv_bfloat16 h2 = __float2bfloat16(v.z), h3 = __float2bfloat16(v.w);
        __nv_bfloat16 e0 = __float2bfloat16(v.x - __bfloat162float(h0));
        __nv_bfloat16 e1 = __float2bfloat16(v.y - __bfloat162float(h1));
        __nv_bfloat16 e2 = __float2bfloat16(v.z - __bfloat162float(h2));
        __nv_bfloat16 e3 = __float2bfloat16(v.w - __bfloat162float(h3));
        uint32_t hi01 = ((uint32_t)__bfloat16_as_ushort(h1) << 16) | __bfloat16_as_ushort(h0);
        uint32_t hi23 = ((uint32_t)__bfloat16_as_ushort(h3) << 16) | __bfloat16_as_ushort(h2);
        uint32_t lo01 = ((uint32_t)__bfloat16_as_ushort(e1) << 16) | __bfloat16_as_ushort(e0);
        uint32_t lo23 = ((uint32_t)__bfloat16_as_ushort(e3) << 16) | __bfloat16_as_ushort(e2);
        int eo = r * SPAD + g * 4;
        *(uint2*)(hi + eo) = make_uint2(hi01, hi23);
        *(uint2*)(lo + eo) = make_uint2(lo01, lo23);
    }
}

// One 128x128x128 product accumulated into acc (3-term bf16 hi/lo emulation)
__device__ __forceinline__ void compute_product(
    const __nv_bfloat16* __restrict__ Ahi, const __nv_bfloat16* __restrict__ Alo,
    const __nv_bfloat16* __restrict__ Whi, const __nv_bfloat16* __restrict__ Wlo,
    float acc[4][4][4], int mw, int nw, int lane)
{
    const int grp = lane >> 2, qp = lane & 3;
    #pragma unroll
    for (int ks = 0; ks < 8; ++ks) {
        const int kb = ks * 16 + qp * 2;
        uint32_t ah[4][4], al[4][4], wh[4][2], wl[4][2];
        #pragma unroll
        for (int i = 0; i < 4; ++i) {
            int eo = (mw * 64 + i * 16 + grp) * SPAD + kb;
            ah[i][0] = *(const uint32_t*)(Ahi + eo);
            ah[i][1] = *(const uint32_t*)(Ahi + eo + 8 * SPAD);
            ah[i][2] = *(const uint32_t*)(Ahi + eo + 8);
            ah[i][3] = *(const uint32_t*)(Ahi + eo + 8 * SPAD + 8);
            al[i][0] = *(const uint32_t*)(Alo + eo);
            al[i][1] = *(const uint32_t*)(Alo + eo + 8 * SPAD);
            al[i][2] = *(const uint32_t*)(Alo + eo + 8);
            al[i][3] = *(const uint32_t*)(Alo + eo + 8 * SPAD + 8);
        }
        #pragma unroll
        for (int j = 0; j < 4; ++j) {
            int eo = (nw * 32 + j * 8 + grp) * SPAD + kb;
            wh[j][0] = *(const uint32_t*)(Whi + eo);
            wh[j][1] = *(const uint32_t*)(Whi + eo + 8);
            wl[j][0] = *(const uint32_t*)(Wlo + eo);
            wl[j][1] = *(const uint32_t*)(Wlo + eo + 8);
        }
        #pragma unroll
        for (int i = 0; i < 4; ++i)
            #pragma unroll
            for (int j = 0; j < 4; ++j) {
                mma16816(acc[i][j], ah[i], wh[j]);
                mma16816(acc[i][j], al[i], wh[j]);
                mma16816(acc[i][j], ah[i], wl[j]);
            }
    }
}

#define ZERO_ACC(a) do {                                       \
    _Pragma("unroll") for (int i = 0; i < 4; ++i)              \
    _Pragma("unroll") for (int j = 0; j < 4; ++j)              \
    _Pragma("unroll") for (int q = 0; q < 4; ++q) (a)[i][j][q] = 0.f; } while (0)

// ---------------- single-product GEMM (xh = x @ Wp^T + bp) ----------------
__global__ void __launch_bounds__(256, 1)
gemm_one(const float* __restrict__ A, const float* __restrict__ W1,
         const float* __restrict__ bias, float* __restrict__ out)
{
    extern __shared__ __align__(16) __nv_bfloat16 smem[];
    __nv_bfloat16* Ahi = smem;
    __nv_bfloat16* Alo = Ahi + TILE_ELEMS;
    __nv_bfloat16* Whi = Alo + TILE_ELEMS;
    __nv_bfloat16* Wlo = Whi + TILE_ELEMS;

    const int tid = threadIdx.x, wid = tid >> 5, lane = tid & 31;
    const int mw = wid >> 2, nw = wid & 3;
    const int rowBase = blockIdx.x * MT;

    float acc[4][4][4];
    ZERO_ACC(acc);

    load_cvt(A, rowBase, NN, Ahi, Alo, tid);
    load_cvt(W1, 0, DD, Whi, Wlo, tid);
    __syncthreads();
    compute_product(Ahi, Alo, Whi, Wlo, acc, mw, nw, lane);

    const int grp = lane >> 2, qp = lane & 3;
    #pragma unroll
    for (int i = 0; i < 4; ++i) {
        int r0 = rowBase + mw * 64 + i * 16 + grp;
        #pragma unroll
        for (int j = 0; j < 4; ++j) {
            int col = nw * 32 + j * 8 + qp * 2;
            float2 bb = *(const float2*)(bias + col);
            if (r0 < NN)
                *(float2*)(out + r0 * DD + col) =
                    make_float2(acc[i][j][0] + bb.x, acc[i][j][1] + bb.y);
            if (r0 + 8 < NN)
                *(float2*)(out + (r0 + 8) * DD + col) =
                    make_float2(acc[i][j][2] + bb.x, acc[i][j][3] + bb.y);
        }
    }
}

// ---------------- pair kernel: p1 = xh@Wc0^T, p2 = xh@Wroot^T (raw) --------
// Loads the xh A-tile ONCE; overlaps (on another stream) with aggregate.
__global__ void __launch_bounds__(256, 1)
gemm_pair(const float* __restrict__ Wc0, const float* __restrict__ Wroot)
{
    extern __shared__ __align__(16) __nv_bfloat16 smem[];
    __nv_bfloat16* Ahi = smem;
    __nv_bfloat16* Alo = Ahi + TILE_ELEMS;
    __nv_bfloat16* Whi = Alo + TILE_ELEMS;
    __nv_bfloat16* Wlo = Whi + TILE_ELEMS;

    const int tid = threadIdx.x, wid = tid >> 5, lane = tid & 31;
    const int mw = wid >> 2, nw = wid & 3;
    const int grp = lane >> 2, qp = lane & 3;
    const int rowBase = blockIdx.x * MT;

    float acc[4][4][4];
    ZERO_ACC(acc);

    load_cvt(g_xh, rowBase, NN, Ahi, Alo, tid);
    load_cvt(Wc0, 0, DD, Whi, Wlo, tid);
    __syncthreads();
    compute_product(Ahi, Alo, Whi, Wlo, acc, mw, nw, lane);

    #pragma unroll
    for (int i = 0; i < 4; ++i) {
        int r0 = rowBase + mw * 64 + i * 16 + grp;
        #pragma unroll
        for (int j = 0; j < 4; ++j) {
            int col = nw * 32 + j * 8 + qp * 2;
            if (r0 < NN)
                *(float2*)(g_p1 + r0 * DD + col) = make_float2(acc[i][j][0], acc[i][j][1]);
            if (r0 + 8 < NN)
                *(float2*)(g_p1 + (r0 + 8) * DD + col) = make_float2(acc[i][j][2], acc[i][j][3]);
        }
    }
    ZERO_ACC(acc);
    __syncthreads();
    load_cvt(Wroot, 0, DD, Whi, Wlo, tid);     // A tile still holds xh
    __syncthreads();
    compute_product(Ahi, Alo, Whi, Wlo, acc, mw, nw, lane);

    #pragma unroll
    for (int i = 0; i < 4; ++i) {
        int r0 = rowBase + mw * 64 + i * 16 + grp;
        #pragma unroll
        for (int j = 0; j < 4; ++j) {
            int col = nw * 32 + j * 8 + qp * 2;
            if (r0 < NN)
                *(float2*)(g_p2 + r0 * DD + col) = make_float2(acc[i][j][0], acc[i][j][1]);
            if (r0 + 8 < NN)
                *(float2*)(g_p2 + (r0 + 8) * DD + col) = make_float2(acc[i][j][2], acc[i][j][3]);
        }
    }
}

// ---------------- tail kernel: o1, o2, s, o3 ----------------
// o1 = lrelu(p1 + Tx1@Wc1^T + bc)      (p1 read in epilogue; o1 in registers)
// o2 = lrelu(p2 + mean@Wrel^T + brel)
// s  = o1 + o2  (cvt to bf16 hi/lo in A tiles)
// o3 = s@Wl^T + bl -> out
__global__ void __launch_bounds__(256, 1)
gemm_tail(const float* __restrict__ Wc1, const float* __restrict__ bc,
          const float* __restrict__ Wrel, const float* __restrict__ brel,
          const float* __restrict__ Wl, const float* __restrict__ bl,
          float* __restrict__ out)
{
    extern __shared__ __align__(16) __nv_bfloat16 smem[];
    __nv_bfloat16* Ahi = smem;
    __nv_bfloat16* Alo = Ahi + TILE_ELEMS;
    __nv_bfloat16* Whi = Alo + TILE_ELEMS;
    __nv_bfloat16* Wlo = Whi + TILE_ELEMS;

    const int tid = threadIdx.x, wid = tid >> 5, lane = tid & 31;
    const int mw = wid >> 2, nw = wid & 3;
    const int grp = lane >> 2, qp = lane & 3;
    const int rowBase = blockIdx.x * MT;

    float acc[4][4][4], o1r[4][4][4];
    ZERO_ACC(acc);

    // P1: Tx1 @ Wc1
    load_cvt(g_Tx1, rowBase, NN, Ahi, Alo, tid);
    load_cvt(Wc1, 0, DD, Whi, Wlo, tid);
    __syncthreads();
    compute_product(Ahi, Alo, Whi, Wlo, acc, mw, nw, lane);

    // epilogue 1: o1 = lrelu(acc + p1 + bc)   (registers)
    #pragma unroll
    for (int i = 0; i < 4; ++i) {
        int r0 = rowBase + mw * 64 + i * 16 + grp;
        #pragma unroll
        for (int j = 0; j < 4; ++j) {
            int col = nw * 32 + j * 8 + qp * 2;
            float2 bb = *(const float2*)(bc + col);
            float2 pa = (r0 < NN) ? *(const float2*)(g_p1 + r0 * DD + col)
                                  : make_float2(0.f, 0.f);
            float2 pb = (r0 + 8 < NN) ? *(const float2*)(g_p1 + (r0 + 8) * DD + col)
                                      : make_float2(0.f, 0.f);
            float v0 = acc[i][j][0] + pa.x + bb.x, v1 = acc[i][j][1] + pa.y + bb.y;
            float v2 = acc[i][j][2] + pb.x + bb.x, v3 = acc[i][j][3] + pb.y + bb.y;
            o1r[i][j][0] = (v0 > 0.f) ? v0 : 0.01f * v0;
            o1r[i][j][1] = (v1 > 0.f) ? v1 : 0.01f * v1;
            o1r[i][j][2] = (v2 > 0.f) ? v2 : 0.01f * v2;
            o1r[i][j][3] = (v3 > 0.f) ? v3 : 0.01f * v3;
        }
    }
    ZERO_ACC(acc);
    __syncthreads();

    // P2: mean @ Wrel
    load_cvt(g_mean, rowBase, NN, Ahi, Alo, tid);
    load_cvt(Wrel, 0, DD, Whi, Wlo, tid);
    __syncthreads();
    compute_product(Ahi, Alo, Whi, Wlo, acc, mw, nw, lane);
    __syncthreads();   // all A reads done before s overwrites A tiles

    // epilogue 2: s = o1 + lrelu(acc + p2 + brel) -> bf16 hi/lo into A tiles
    #pragma unroll
    for (int i = 0; i < 4; ++i) {
        int lr0 = mw * 64 + i * 16 + grp;
        int r0 = rowBase + lr0;
        #pragma unroll
        for (int j = 0; j < 4; ++j) {
            int col = nw * 32 + j * 8 + qp * 2;
            float2 bb = *(const float2*)(brel + col);
            float2 pa = (r0 < NN) ? *(const float2*)(g_p2 + r0 * DD + col)
                                  : make_float2(0.f, 0.f);
            float2 pb = (r0 + 8 < NN) ? *(const float2*)(g_p2 + (r0 + 8) * DD + col)
                                      : make_float2(0.f, 0.f);
            float v0 = acc[i][j][0] + pa.x + bb.x, v1 = acc[i][j][1] + pa.y + bb.y;
            float v2 = acc[i][j][2] + pb.x + bb.x, v3 = acc[i][j][3] + pb.y + bb.y;
            v0 = (v0 > 0.f) ? v0 : 0.01f * v0;
            v1 = (v1 > 0.f) ? v1 : 0.01f * v1;
            v2 = (v2 > 0.f) ? v2 : 0.01f * v2;
            v3 = (v3 > 0.f) ? v3 : 0.01f * v3;
            float s0 = o1r[i][j][0] + v0, s1 = o1r[i][j][1] + v1;
            float s2 = o1r[i][j][2] + v2, s3 = o1r[i][j][3] + v3;
            uint32_t h01 = pack_hi(s0, s1);
            uint32_t h23 = pack_hi(s2, s3);
            __nv_bfloat16 h0 = __float2bfloat16(s0), h1 = __float2bfloat16(s1);
            __nv_bfloat16 h2 = __float2bfloat16(s2), h3 = __float2bfloat16(s3);
            uint32_t l01 = pack_hi(s0 - __bfloat162float(h0), s1 - __bfloat162float(h1));
            uint32_t l23 = pack_hi(s2 - __bfloat162float(h2), s3 - __bfloat162float(h3));
            int eo0 = lr0 * SPAD + col;
            int eo1 = (lr0 + 8) * SPAD + col;
            *(uint32_t*)(Ahi + eo0) = h01;
            *(uint32_t*)(Alo + eo0) = l01;
            *(uint32_t*)(Ahi + eo1) = h23;
            *(uint32_t*)(Alo + eo1) = l23;
        }
    }
    ZERO_ACC(acc);
    // P3: s @ Wl
    load_cvt(Wl, 0, DD, Whi, Wlo, tid);
    __syncthreads();
    compute_product(Ahi, Alo, Whi, Wlo, acc, mw, nw, lane);

    // epilogue 3: o3 = acc + bl -> out
    #pragma unroll
    for (int i = 0; i < 4; ++i) {
        int r0 = rowBase + mw * 64 + i * 16 + grp;
        #pragma unroll
        for (int j = 0; j < 4; ++j) {
            int col = nw * 32 + j * 8 + qp * 2;
            float2 bb = *(const float2*)(bl + col);
            if (r0 < NN)
                *(float2*)(out + r0 * DD + col) =
                    make_float2(acc[i][j][0] + bb.x, acc[i][j][1] + bb.y);
            if (r0 + 8 < NN)
                *(float2*)(out + (r0 + 8) * DD + col) =
                    make_float2(acc[i][j][2] + bb.x, acc[i][j][3] + bb.y);
        }
    }
}

// ---------------- launch ----------------
extern "C" void kernel_launch(void* const* d_in, const int* in_sizes, int n_in,
                              void* d_out, int out_size)
{
    (void)in_sizes; (void)n_in;
    const float* x    = (const float*)d_in[1];
    const int*   ei   = (const int*)  d_in[2];
    const float* ew   = (const float*)d_in[3];
    const float* Wp   = (const float*)d_in[4];
    const float* bp   = (const float*)d_in[5];
    const float* Wc0  = (const float*)d_in[6];
    const float* Wc1  = (const float*)d_in[7];
    const float* bc   = (const float*)d_in[8];
    const float* Wrel = (const float*)d_in[9];
    const float* brel = (const float*)d_in[10];
    const float* Wroot= (const float*)d_in[11];
    const float* Wl   = (const float*)d_in[12];
    const float* bl   = (const float*)d_in[13];
    float* out = (float*)d_out;

    void* p_xh;
    cudaGetSymbolAddress(&p_xh, g_xh);

    static cudaStream_t s2 = nullptr, s3 = nullptr;
    static cudaEvent_t ev1 = nullptr, evXH = nullptr, evAgg = nullptr, evCpy = nullptr;
    static bool attrDone = false;
    const int smemB = 4 * TILE_ELEMS * (int)sizeof(__nv_bfloat16);   // 139264 B
    if (!s2) {
        cudaStreamCreateWithFlags(&s2, cudaStreamNonBlocking);
        cudaStreamCreateWithFlags(&s3, cudaStreamNonBlocking);
        cudaEventCreateWithFlags(&ev1,   cudaEventDisableTiming);
        cudaEventCreateWithFlags(&evXH,  cudaEventDisableTiming);
        cudaEventCreateWithFlags(&evAgg, cudaEventDisableTiming);
        cudaEventCreateWithFlags(&evCpy, cudaEventDisableTiming);
    }
    if (!attrDone) {
        cudaFuncSetAttribute(gemm_one,
                             cudaFuncAttributeMaxDynamicSharedMemorySize, smemB);
        cudaFuncSetAttribute(gemm_pair,
                             cudaFuncAttributeMaxDynamicSharedMemorySize, smemB);
        cudaFuncSetAttribute(gemm_tail,
                             cudaFuncAttributeMaxDynamicSharedMemorySize, smemB);
        attrDone = true;
    }

    const int TB = 256;

    // ---- fork ----
    cudaEventRecord(ev1, 0);
    cudaStreamWaitEvent(s2, ev1, 0);
    cudaStreamWaitEvent(s3, ev1, 0);

    // s3: his = x (copy engine, fully parallel)
    if (out_size >= 2 * NN * DD)
        cudaMemcpyAsync(out, x, (size_t)NN * DD * sizeof(float),
                        cudaMemcpyDeviceToDevice, s3);
    cudaEventRecord(evCpy, s3);

    // s2: CSR build chain
    zero_kernel<<<(NN + TB - 1) / TB, TB, 0, s2>>>();
    hist_kernel<<<(EE + TB - 1) / TB, TB, 0, s2>>>(ei, ew);
    dis_kernel<<<(NN + TB - 1) / TB, TB, 0, s2>>>();
    scan1_kernel<<<NB_SCAN, 512, 0, s2>>>();
    scan2_kernel<<<1, 128, 0, s2>>>();
    scan3_kernel<<<(NN + TB - 1) / TB, TB, 0, s2>>>();
    fill_kernel<<<(EE + TB - 1) / TB, TB, 0, s2>>>(ei, ew);

    // s0: xh = x @ Wp^T + bp
    gemm_one<<<GTILES, TB, smemB>>>(x, Wp, bp, (float*)p_xh);
    cudaEventRecord(evXH, 0);

    // s2: aggregate (needs CSR + xh) — overlaps with gemm_pair on s0
    cudaStreamWaitEvent(s2, evXH, 0);
    aggregate_kernel<<<(NN * 32 + TB - 1) / TB, TB, 0, s2>>>();
    cudaEventRecord(evAgg, s2);

    // s0: p1 = xh@Wc0, p2 = xh@Wroot (concurrent with aggregate)
    gemm_pair<<<GTILES, TB, smemB>>>(Wc0, Wroot);

    // ---- join, then tail ----
    cudaStreamWaitEvent(0, evAgg, 0);
    float* o3 = out + ((out_size >= 2 * NN * DD) ? (NN * DD) : 0);
    gemm_tail<<<GTILES, TB, smemB>>>(Wc1, bc, Wrel, brel, Wl, bl, o3);
    cudaStreamWaitEvent(0, evCpy, 0);
}

// round 11
// speedup vs baseline: 2.3532x; 1.0180x over previous
#include <cuda_runtime.h>
#include <cuda_bf16.h>
#include <cstdint>

#define NN 50000
#define EE 800000
#define DD 128
#define MT 64
#define GTILES ((NN + MT - 1) / MT)     // 782
#define NB_SCAN ((NN + 511) / 512)      // 98
#define SPAD 136                         // bf16 elems per smem row (conflict-free)
#define A_ELEMS (64 * SPAD)              // 8704  bf16 per A tile
#define W_ELEMS (128 * SPAD)             // 17408 bf16 per W tile

// ---------------- scratch (device globals: allocation-free) ----------------
__device__ float g_xh[NN * DD];
__device__ float g_Tx1[NN * DD];
__device__ float g_mean[NN * DD];
__device__ float g_p1[NN * DD];          // xh @ Wc0^T   (raw partial)
__device__ float g_p2[NN * DD];          // xh @ Wroot^T (raw partial)
__device__ float g_deg[NN];
__device__ float g_dis[NN];
__device__ int   g_cnt[NN];
__device__ int   g_fill[NN];
__device__ int   g_rowptr[NN + 1];
__device__ int   g_bsum[128];
__device__ int   g_csrc[EE];
__device__ float g_cw[EE];

// ---------------- small kernels (CSR build) ----------------
__global__ void zero_kernel() {
    int i = blockIdx.x * blockDim.x + threadIdx.x;
    if (i < NN) { g_deg[i] = 0.f; g_cnt[i] = 0; g_fill[i] = 0; }
}
__global__ void hist_kernel(const int* __restrict__ ei, const float* __restrict__ ew) {
    int e = blockIdx.x * blockDim.x + threadIdx.x;
    if (e < EE) {
        atomicAdd(&g_deg[ei[e]], ew[e]);
        atomicAdd(&g_cnt[ei[EE + e]], 1);
    }
}
__global__ void dis_kernel() {
    int i = blockIdx.x * blockDim.x + threadIdx.x;
    if (i < NN) {
        float d = g_deg[i];
        g_dis[i] = (d > 0.f) ? rsqrtf(d) : 0.f;
    }
}
__global__ void scan1_kernel() {
    __shared__ int sm[512];
    int t = threadIdx.x, b = blockIdx.x;
    int i = b * 512 + t;
    int v = (i < NN) ? g_cnt[i] : 0;
    sm[t] = v;
    __syncthreads();
    #pragma unroll
    for (int off = 1; off < 512; off <<= 1) {
        int x = (t >= off) ? sm[t - off] : 0;
        __syncthreads();
        if (t >= off) sm[t] += x;
        __syncthreads();
    }
    if (i < NN) g_rowptr[i + 1] = sm[t];
    if (t == 511) g_bsum[b] = sm[511];
}
__global__ void scan2_kernel() {
    __shared__ int sm[128];
    int t = threadIdx.x;
    int v = (t < NB_SCAN) ? g_bsum[t] : 0;
    sm[t] = v;
    __syncthreads();
    #pragma unroll
    for (int off = 1; off < 128; off <<= 1) {
        int x = (t >= off) ? sm[t - off] : 0;
        __syncthreads();
        sm[t] += x;
        __syncthreads();
    }
    if (t < NB_SCAN) g_bsum[t] = sm[t] - v;
}
__global__ void scan3_kernel() {
    int i = blockIdx.x * blockDim.x + threadIdx.x;
    if (i < NN) {
        if (i == 0) g_rowptr[0] = 0;
        g_rowptr[i + 1] += g_bsum[i >> 9];
    }
}
__global__ void fill_kernel(const int* __restrict__ ei, const float* __restrict__ ew) {
    int e = blockIdx.x * blockDim.x + threadIdx.x;
    if (e < EE) {
        int d = ei[EE + e];
        int pos = g_rowptr[d] + atomicAdd(&g_fill[d], 1);
        g_csrc[pos] = ei[e];
        g_cw[pos]   = ew[e];
    }
}
__global__ void aggregate_kernel() {
    int warp = (blockIdx.x * blockDim.x + threadIdx.x) >> 5;
    int lane = threadIdx.x & 31;
    if (warp >= NN) return;
    int beg = g_rowptr[warp], end = g_rowptr[warp + 1];
    float dd = g_dis[warp];
    float4 aT = make_float4(0.f, 0.f, 0.f, 0.f);
    float4 aM = make_float4(0.f, 0.f, 0.f, 0.f);
    const float4* xh4 = (const float4*)g_xh;
    #pragma unroll 4
    for (int e = beg; e < end; ++e) {
        int s = g_csrc[e];
        float w = g_cw[e];
        float nrm = -g_dis[s] * w * dd;
        float4 v = xh4[s * 32 + lane];
        aT.x += nrm * v.x; aT.y += nrm * v.y; aT.z += nrm * v.z; aT.w += nrm * v.w;
        aM.x += w   * v.x; aM.y += w   * v.y; aM.z += w   * v.z; aM.w += w   * v.w;
    }
    ((float4*)g_Tx1)[warp * 32 + lane] = aT;
    float inv = 1.0f / fmaxf((float)g_cnt[warp], 1.0f);
    aM.x *= inv; aM.y *= inv; aM.z *= inv; aM.w *= inv;
    ((float4*)g_mean)[warp * 32 + lane] = aM;
}

// ---------------- mma.sync m16n8k16 bf16 ----------------
__device__ __forceinline__ void mma16816(float* c, const uint32_t* a, const uint32_t* b) {
    asm volatile(
        "mma.sync.aligned.m16n8k16.row.col.f32.bf16.bf16.f32 "
        "{%0,%1,%2,%3}, {%4,%5,%6,%7}, {%8,%9}, {%0,%1,%2,%3};"
        : "+f"(c[0]), "+f"(c[1]), "+f"(c[2]), "+f"(c[3])
        : "r"(a[0]), "r"(a[1]), "r"(a[2]), "r"(a[3]), "r"(b[0]), "r"(b[1]));
}

__device__ __forceinline__ uint32_t pack_hi(float a, float b) {
    __nv_bfloat16 x = __float2bfloat16(a), y = __float2bfloat16(b);
    return ((uint32_t)__bfloat16_as_ushort(y) << 16) | __bfloat16_as_ushort(x);
}

// fp32 [rows x 128] chunk -> hi/lo bf16 row-major smem tiles (stride SPAD)
template <int ROWS>
__device__ __forceinline__ void load_cvt(const float* __restrict__ src, int rowBase,
                                         int rowLim, __nv_bfloat16* hi,
                                         __nv_bfloat16* lo, int tid)
{
    const float4* s4 = (const float4*)src;
    #pragma unroll
    for (int it = 0; it < ROWS / 8; ++it) {
        int idx = tid + it * 256;
        int r = idx >> 5, g = idx & 31;
        int gr = rowBase + r;
        float4 v = make_float4(0.f, 0.f, 0.f, 0.f);
        if (gr < rowLim) v = s4[gr * 32 + g];
        __nv_bfloat16 h0 = __float2bfloat16(v.x), h1 = __float2bfloat16(v.y);
        __nv_bfloat16 h2 = __float2bfloat16(v.z), h3 = __float2bfloat16(v.w);
        __nv_bfloat16 e0 = __float2bfloat16(v.x - __bfloat162float(h0));
        __nv_bfloat16 e1 = __float2bfloat16(v.y - __bfloat162float(h1));
        __nv_bfloat16 e2 = __float2bfloat16(v.z - __bfloat162float(h2));
        __nv_bfloat16 e3 = __float2bfloat16(v.w - __bfloat162float(h3));
        uint32_t hi01 = ((uint32_t)__bfloat16_as_ushort(h1) << 16) | __bfloat16_as_ushort(h0);
        uint32_t hi23 = ((uint32_t)__bfloat16_as_ushort(h3) << 16) | __bfloat16_as_ushort(h2);
        uint32_t lo01 = ((uint32_t)__bfloat16_as_ushort(e1) << 16) | __bfloat16_as_ushort(e0);
        uint32_t lo23 = ((uint32_t)__bfloat16_as_ushort(e3) << 16) | __bfloat16_as_ushort(e2);
        int eo = r * SPAD + g * 4;
        *(uint2*)(hi + eo) = make_uint2(hi01, hi23);
        *(uint2*)(lo + eo) = make_uint2(lo01, lo23);
    }
}

// One 64x128x128 product accumulated into acc (3-term bf16 hi/lo emulation)
// Warp grid 2(m) x 4(n); warp tile 32x32.
__device__ __forceinline__ void compute_product(
    const __nv_bfloat16* __restrict__ Ahi, const __nv_bfloat16* __restrict__ Alo,
    const __nv_bfloat16* __restrict__ Whi, const __nv_bfloat16* __restrict__ Wlo,
    float acc[2][4][4], int mw, int nw, int lane)
{
    const int grp = lane >> 2, qp = lane & 3;
    #pragma unroll
    for (int ks = 0; ks < 8; ++ks) {
        const int kb = ks * 16 + qp * 2;
        uint32_t ah[2][4], al[2][4], wh[4][2], wl[4][2];
        #pragma unroll
        for (int i = 0; i < 2; ++i) {
            int eo = (mw * 32 + i * 16 + grp) * SPAD + kb;
            ah[i][0] = *(const uint32_t*)(Ahi + eo);
            ah[i][1] = *(const uint32_t*)(Ahi + eo + 8 * SPAD);
            ah[i][2] = *(const uint32_t*)(Ahi + eo + 8);
            ah[i][3] = *(const uint32_t*)(Ahi + eo + 8 * SPAD + 8);
            al[i][0] = *(const uint32_t*)(Alo + eo);
            al[i][1] = *(const uint32_t*)(Alo + eo + 8 * SPAD);
            al[i][2] = *(const uint32_t*)(Alo + eo + 8);
            al[i][3] = *(const uint32_t*)(Alo + eo + 8 * SPAD + 8);
        }
        #pragma unroll
        for (int j = 0; j < 4; ++j) {
            int eo = (nw * 32 + j * 8 + grp) * SPAD + kb;
            wh[j][0] = *(const uint32_t*)(Whi + eo);
            wh[j][1] = *(const uint32_t*)(Whi + eo + 8);
            wl[j][0] = *(const uint32_t*)(Wlo + eo);
            wl[j][1] = *(const uint32_t*)(Wlo + eo + 8);
        }
        #pragma unroll
        for (int i = 0; i < 2; ++i)
            #pragma unroll
            for (int j = 0; j < 4; ++j) {
                mma16816(acc[i][j], ah[i], wh[j]);
                mma16816(acc[i][j], al[i], wh[j]);
                mma16816(acc[i][j], ah[i], wl[j]);
            }
    }
}

#define ZERO_ACC(a) do {                                       \
    _Pragma("unroll") for (int i = 0; i < 2; ++i)              \
    _Pragma("unroll") for (int j = 0; j < 4; ++j)              \
    _Pragma("unroll") for (int q = 0; q < 4; ++q) (a)[i][j][q] = 0.f; } while (0)

// smem bytes: (2*A + 2*W) tiles = (2*8704 + 2*17408)*2 = 104448 B -> 2 CTAs/SM
#define SMEM_BYTES ((2 * A_ELEMS + 2 * W_ELEMS) * (int)sizeof(__nv_bfloat16))

// ---------------- single-product GEMM (xh = x @ Wp^T + bp) ----------------
__global__ void __launch_bounds__(256, 2)
gemm_one(const float* __restrict__ A, const float* __restrict__ W1,
         const float* __restrict__ bias, float* __restrict__ out)
{
    extern __shared__ __align__(16) __nv_bfloat16 smem[];
    __nv_bfloat16* Ahi = smem;
    __nv_bfloat16* Alo = Ahi + A_ELEMS;
    __nv_bfloat16* Whi = Alo + A_ELEMS;
    __nv_bfloat16* Wlo = Whi + W_ELEMS;

    const int tid = threadIdx.x, wid = tid >> 5, lane = tid & 31;
    const int mw = wid >> 2, nw = wid & 3;
    const int rowBase = blockIdx.x * MT;

    float acc[2][4][4];
    ZERO_ACC(acc);

    load_cvt<64>(A, rowBase, NN, Ahi, Alo, tid);
    load_cvt<128>(W1, 0, DD, Whi, Wlo, tid);
    __syncthreads();
    compute_product(Ahi, Alo, Whi, Wlo, acc, mw, nw, lane);

    const int grp = lane >> 2, qp = lane & 3;
    #pragma unroll
    for (int i = 0; i < 2; ++i) {
        int r0 = rowBase + mw * 32 + i * 16 + grp;
        #pragma unroll
        for (int j = 0; j < 4; ++j) {
            int col = nw * 32 + j * 8 + qp * 2;
            float2 bb = *(const float2*)(bias + col);
            if (r0 < NN)
                *(float2*)(out + r0 * DD + col) =
                    make_float2(acc[i][j][0] + bb.x, acc[i][j][1] + bb.y);
            if (r0 + 8 < NN)
                *(float2*)(out + (r0 + 8) * DD + col) =
                    make_float2(acc[i][j][2] + bb.x, acc[i][j][3] + bb.y);
        }
    }
}

// ---------------- pair kernel: p1 = xh@Wc0^T, p2 = xh@Wroot^T (raw) --------
__global__ void __launch_bounds__(256, 2)
gemm_pair(const float* __restrict__ Wc0, const float* __restrict__ Wroot)
{
    extern __shared__ __align__(16) __nv_bfloat16 smem[];
    __nv_bfloat16* Ahi = smem;
    __nv_bfloat16* Alo = Ahi + A_ELEMS;
    __nv_bfloat16* Whi = Alo + A_ELEMS;
    __nv_bfloat16* Wlo = Whi + W_ELEMS;

    const int tid = threadIdx.x, wid = tid >> 5, lane = tid & 31;
    const int mw = wid >> 2, nw = wid & 3;
    const int grp = lane >> 2, qp = lane & 3;
    const int rowBase = blockIdx.x * MT;

    float acc[2][4][4];
    ZERO_ACC(acc);

    load_cvt<64>(g_xh, rowBase, NN, Ahi, Alo, tid);
    load_cvt<128>(Wc0, 0, DD, Whi, Wlo, tid);
    __syncthreads();
    compute_product(Ahi, Alo, Whi, Wlo, acc, mw, nw, lane);

    #pragma unroll
    for (int i = 0; i < 2; ++i) {
        int r0 = rowBase + mw * 32 + i * 16 + grp;
        #pragma unroll
        for (int j = 0; j < 4; ++j) {
            int col = nw * 32 + j * 8 + qp * 2;
            if (r0 < NN)
                *(float2*)(g_p1 + r0 * DD + col) = make_float2(acc[i][j][0], acc[i][j][1]);
            if (r0 + 8 < NN)
                *(float2*)(g_p1 + (r0 + 8) * DD + col) = make_float2(acc[i][j][2], acc[i][j][3]);
        }
    }
    ZERO_ACC(acc);
    __syncthreads();
    load_cvt<128>(Wroot, 0, DD, Whi, Wlo, tid);   // A tile still holds xh
    __syncthreads();
    compute_product(Ahi, Alo, Whi, Wlo, acc, mw, nw, lane);

    #pragma unroll
    for (int i = 0; i < 2; ++i) {
        int r0 = rowBase + mw * 32 + i * 16 + grp;
        #pragma unroll
        for (int j = 0; j < 4; ++j) {
            int col = nw * 32 + j * 8 + qp * 2;
            if (r0 < NN)
                *(float2*)(g_p2 + r0 * DD + col) = make_float2(acc[i][j][0], acc[i][j][1]);
            if (r0 + 8 < NN)
                *(float2*)(g_p2 + (r0 + 8) * DD + col) = make_float2(acc[i][j][2], acc[i][j][3]);
        }
    }
}

// ---------------- tail kernel: o1, o2, s, o3 ----------------
__global__ void __launch_bounds__(256, 2)
gemm_tail(const float* __restrict__ Wc1, const float* __restrict__ bc,
          const float* __restrict__ Wrel, const float* __restrict__ brel,
          const float* __restrict__ Wl, const float* __restrict__ bl,
          float* __restrict__ out)
{
    extern __shared__ __align__(16) __nv_bfloat16 smem[];
    __nv_bfloat16* Ahi = smem;
    __nv_bfloat16* Alo = Ahi + A_ELEMS;
    __nv_bfloat16* Whi = Alo + A_ELEMS;
    __nv_bfloat16* Wlo = Whi + W_ELEMS;

    const int tid = threadIdx.x, wid = tid >> 5, lane = tid & 31;
    const int mw = wid >> 2, nw = wid & 3;
    const int grp = lane >> 2, qp = lane & 3;
    const int rowBase = blockIdx.x * MT;

    float acc[2][4][4], o1r[2][4][4];
    ZERO_ACC(acc);

    // P1: Tx1 @ Wc1
    load_cvt<64>(g_Tx1, rowBase, NN, Ahi, Alo, tid);
    load_cvt<128>(Wc1, 0, DD, Whi, Wlo, tid);
    __syncthreads();
    compute_product(Ahi, Alo, Whi, Wlo, acc, mw, nw, lane);

    // epilogue 1: o1 = lrelu(acc + p1 + bc)   (registers)
    #pragma unroll
    for (int i = 0; i < 2; ++i) {
        int r0 = rowBase + mw * 32 + i * 16 + grp;
        #pragma unroll
        for (int j = 0; j < 4; ++j) {
            int col = nw * 32 + j * 8 + qp * 2;
            float2 bb = *(const float2*)(bc + col);
            float2 pa = (r0 < NN) ? *(const float2*)(g_p1 + r0 * DD + col)
                                  : make_float2(0.f, 0.f);
            float2 pb = (r0 + 8 < NN) ? *(const float2*)(g_p1 + (r0 + 8) * DD + col)
                                      : make_float2(0.f, 0.f);
            float v0 = acc[i][j][0] + pa.x + bb.x, v1 = acc[i][j][1] + pa.y + bb.y;
            float v2 = acc[i][j][2] + pb.x + bb.x, v3 = acc[i][j][3] + pb.y + bb.y;
            o1r[i][j][0] = (v0 > 0.f) ? v0 : 0.01f * v0;
            o1r[i][j][1] = (v1 > 0.f) ? v1 : 0.01f * v1;
            o1r[i][j][2] = (v2 > 0.f) ? v2 : 0.01f * v2;
            o1r[i][j][3] = (v3 > 0.f) ? v3 : 0.01f * v3;
        }
    }
    ZERO_ACC(acc);
    __syncthreads();

    // P2: mean @ Wrel
    load_cvt<64>(g_mean, rowBase, NN, Ahi, Alo, tid);
    load_cvt<128>(Wrel, 0, DD, Whi, Wlo, tid);
    __syncthreads();
    compute_product(Ahi, Alo, Whi, Wlo, acc, mw, nw, lane);
    __syncthreads();   // all A reads done before s overwrites A tiles

    // epilogue 2: s = o1 + lrelu(acc + p2 + brel) -> bf16 hi/lo into A tiles
    #pragma unroll
    for (int i = 0; i < 2; ++i) {
        int lr0 = mw * 32 + i * 16 + grp;
        int r0 = rowBase + lr0;
        #pragma unroll
        for (int j = 0; j < 4; ++j) {
            int col = nw * 32 + j * 8 + qp * 2;
            float2 bb = *(const float2*)(brel + col);
            float2 pa = (r0 < NN) ? *(const float2*)(g_p2 + r0 * DD + col)
                                  : make_float2(0.f, 0.f);
            float2 pb = (r0 + 8 < NN) ? *(const float2*)(g_p2 + (r0 + 8) * DD + col)
                                      : make_float2(0.f, 0.f);
            float v0 = acc[i][j][0] + pa.x + bb.x, v1 = acc[i][j][1] + pa.y + bb.y;
            float v2 = acc[i][j][2] + pb.x + bb.x, v3 = acc[i][j][3] + pb.y + bb.y;
            v0 = (v0 > 0.f) ? v0 : 0.01f * v0;
            v1 = (v1 > 0.f) ? v1 : 0.01f * v1;
            v2 = (v2 > 0.f) ? v2 : 0.01f * v2;
            v3 = (v3 > 0.f) ? v3 : 0.01f * v3;
            float s0 = o1r[i][j][0] + v0, s1 = o1r[i][j][1] + v1;
            float s2 = o1r[i][j][2] + v2, s3 = o1r[i][j][3] + v3;
            uint32_t h01 = pack_hi(s0, s1);
            uint32_t h23 = pack_hi(s2, s3);
            __nv_bfloat16 h0 = __float2bfloat16(s0), h1 = __float2bfloat16(s1);
            __nv_bfloat16 h2 = __float2bfloat16(s2), h3 = __float2bfloat16(s3);
            uint32_t l01 = pack_hi(s0 - __bfloat162float(h0), s1 - __bfloat162float(h1));
            uint32_t l23 = pack_hi(s2 - __bfloat162float(h2), s3 - __bfloat162float(h3));
            int eo0 = lr0 * SPAD + col;
            int eo1 = (lr0 + 8) * SPAD + col;
            *(uint32_t*)(Ahi + eo0) = h01;
            *(uint32_t*)(Alo + eo0) = l01;
            *(uint32_t*)(Ahi + eo1) = h23;
            *(uint32_t*)(Alo + eo1) = l23;
        }
    }
    ZERO_ACC(acc);
    // P3: s @ Wl
    load_cvt<128>(Wl, 0, DD, Whi, Wlo, tid);
    __syncthreads();
    compute_product(Ahi, Alo, Whi, Wlo, acc, mw, nw, lane);

    // epilogue 3: o3 = acc + bl -> out
    #pragma unroll
    for (int i = 0; i < 2; ++i) {
        int r0 = rowBase + mw * 32 + i * 16 + grp;
        #pragma unroll
        for (int j = 0; j < 4; ++j) {
            int col = nw * 32 + j * 8 + qp * 2;
            float2 bb = *(const float2*)(bl + col);
            if (r0 < NN)
                *(float2*)(out + r0 * DD + col) =
                    make_float2(acc[i][j][0] + bb.x, acc[i][j][1] + bb.y);
            if (r0 + 8 < NN)
                *(float2*)(out + (r0 + 8) * DD + col) =
                    make_float2(acc[i][j][2] + bb.x, acc[i][j][3] + bb.y);
        }
    }
}

// ---------------- launch ----------------
extern "C" void kernel_launch(void* const* d_in, const int* in_sizes, int n_in,
                              void* d_out, int out_size)
{
    (void)in_sizes; (void)n_in;
    const float* x    = (const float*)d_in[1];
    const int*   ei   = (const int*)  d_in[2];
    const float* ew   = (const float*)d_in[3];
    const float* Wp   = (const float*)d_in[4];
    const float* bp   = (const float*)d_in[5];
    const float* Wc0  = (const float*)d_in[6];
    const float* Wc1  = (const float*)d_in[7];
    const float* bc   = (const float*)d_in[8];
    const float* Wrel = (const float*)d_in[9];
    const float* brel = (const float*)d_in[10];
    const float* Wroot= (const float*)d_in[11];
    const float* Wl   = (const float*)d_in[12];
    const float* bl   = (const float*)d_in[13];
    float* out = (float*)d_out;

    void* p_xh;
    cudaGetSymbolAddress(&p_xh, g_xh);

    static cudaStream_t s2 = nullptr, s3 = nullptr;
    static cudaEvent_t ev1 = nullptr, evXH = nullptr, evAgg = nullptr, evCpy = nullptr;
    static bool attrDone = false;
    if (!s2) {
        cudaStreamCreateWithFlags(&s2, cudaStreamNonBlocking);
        cudaStreamCreateWithFlags(&s3, cudaStreamNonBlocking);
        cudaEventCreateWithFlags(&ev1,   cudaEventDisableTiming);
        cudaEventCreateWithFlags(&evXH,  cudaEventDisableTiming);
        cudaEventCreateWithFlags(&evAgg, cudaEventDisableTiming);
        cudaEventCreateWithFlags(&evCpy, cudaEventDisableTiming);
    }
    if (!attrDone) {
        cudaFuncSetAttribute(gemm_one,
                             cudaFuncAttributeMaxDynamicSharedMemorySize, SMEM_BYTES);
        cudaFuncSetAttribute(gemm_pair,
                             cudaFuncAttributeMaxDynamicSharedMemorySize, SMEM_BYTES);
        cudaFuncSetAttribute(gemm_tail,
                             cudaFuncAttributeMaxDynamicSharedMemorySize, SMEM_BYTES);
        attrDone = true;
    }

    const int TB = 256;

    // ---- fork ----
    cudaEventRecord(ev1, 0);
    cudaStreamWaitEvent(s2, ev1, 0);
    cudaStreamWaitEvent(s3, ev1, 0);

    // s3: his = x (copy engine, fully parallel)
    if (out_size >= 2 * NN * DD)
        cudaMemcpyAsync(out, x, (size_t)NN * DD * sizeof(float),
                        cudaMemcpyDeviceToDevice, s3);
    cudaEventRecord(evCpy, s3);

    // s2: CSR build chain
    zero_kernel<<<(NN + TB - 1) / TB, TB, 0, s2>>>();
    hist_kernel<<<(EE + TB - 1) / TB, TB, 0, s2>>>(ei, ew);
    dis_kernel<<<(NN + TB - 1) / TB, TB, 0, s2>>>();
    scan1_kernel<<<NB_SCAN, 512, 0, s2>>>();
    scan2_kernel<<<1, 128, 0, s2>>>();
    scan3_kernel<<<(NN + TB - 1) / TB, TB, 0, s2>>>();
    fill_kernel<<<(EE + TB - 1) / TB, TB, 0, s2>>>(ei, ew);

    // s0: xh = x @ Wp^T + bp
    gemm_one<<<GTILES, TB, SMEM_BYTES>>>(x, Wp, bp, (float*)p_xh);
    cudaEventRecord(evXH, 0);

    // s2: aggregate (needs CSR + xh) — overlaps with gemm_pair on s0
    cudaStreamWaitEvent(s2, evXH, 0);
    aggregate_kernel<<<(NN * 32 + TB - 1) / TB, TB, 0, s2>>>();
    cudaEventRecord(evAgg, s2);

    // s0: p1 = xh@Wc0, p2 = xh@Wroot (concurrent with aggregate)
    gemm_pair<<<GTILES, TB, SMEM_BYTES>>>(Wc0, Wroot);

    // ---- join, then tail ----
    cudaStreamWaitEvent(0, evAgg, 0);
    float* o3 = out + ((out_size >= 2 * NN * DD) ? (NN * DD) : 0);
    gemm_tail<<<GTILES, TB, SMEM_BYTES>>>(Wc1, bc, Wrel, brel, Wl, bl, o3);
    cudaStreamWaitEvent(0, evCpy, 0);
}